// round 12
// baseline (speedup 1.0000x reference)
#include <cuda_runtime.h>
#include <cuda_fp16.h>
#include <math.h>
#include <stdint.h>

// ---------------- problem constants ----------------
#define BATCH   2
#define SEQ     2048
#define T_TOK   4096
#define DMODEL  2048
#define NHEAD   16
#define QLORA   1536
#define KVLORA  512
#define DN      128
#define DR      64
#define DV      128
#define CDIM    576
#define QF_LD   (NHEAD*CDIM)   // 9216

// ---------------- scratch (static device memory) ----------------
__device__ float g_q_mixed [(size_t)T_TOK * QLORA];
__device__ float g_kv_mixed[(size_t)T_TOK * CDIM];
__device__ float g_q_rope  [(size_t)T_TOK * (NHEAD*DR)];
__device__ float g_scores  [(size_t)BATCH * NHEAD * SEQ * SEQ];

__device__ __half g_hidden [(size_t)T_TOK * DMODEL];
__device__ __half g_wqa    [(size_t)QLORA * DMODEL];
__device__ __half g_wkva   [(size_t)CDIM * DMODEL];
__device__ __half g_wqb    [(size_t)(NHEAD*DN) * QLORA];
__device__ __half g_wqr    [(size_t)(NHEAD*DR) * QLORA];
__device__ __half g_wo     [(size_t)DMODEL * (NHEAD*DV)];
__device__ __half g_kupT   [(size_t)NHEAD * KVLORA * DN];
__device__ __half g_vup    [(size_t)NHEAD * DV * KVLORA];
__device__ __half g_qlat   [(size_t)T_TOK * QLORA];
__device__ __half g_qnope  [(size_t)T_TOK * (NHEAD*DN)];
__device__ __half g_qfull  [(size_t)T_TOK * QF_LD];
__device__ __half g_kfull  [(size_t)T_TOK * CDIM];
__device__ __half g_kvlatT [(size_t)BATCH * KVLORA * SEQ];
__device__ __half g_probs  [(size_t)BATCH * NHEAD * SEQ * SEQ];
__device__ __half g_attn   [(size_t)BATCH * NHEAD * SEQ * KVLORA];
__device__ __half g_attnv  [(size_t)T_TOK * (NHEAD*DV)];

__device__ float g_cos[SEQ * 32];
__device__ float g_sin[SEQ * 32];

// ---------------- helpers ----------------
__device__ __forceinline__ uint32_t smem_u32(const void* p) {
    uint32_t a;
    asm("{ .reg .u64 t; cvta.to.shared.u64 t, %1; cvt.u32.u64 %0, t; }" : "=r"(a) : "l"(p));
    return a;
}
__device__ __forceinline__ void cpa16(uint32_t dst, const void* src, uint32_t sz) {
    asm volatile("cp.async.cg.shared.global [%0], [%1], 16, %2;"
                 :: "r"(dst), "l"(src), "r"(sz) : "memory");
}
__device__ __forceinline__ void ldm4(uint32_t* r, uint32_t a) {
    asm volatile("ldmatrix.sync.aligned.m8n8.x4.shared.b16 {%0,%1,%2,%3}, [%4];"
                 : "=r"(r[0]), "=r"(r[1]), "=r"(r[2]), "=r"(r[3]) : "r"(a));
}
__device__ __forceinline__ void mma16816h(float* c, const uint32_t* a, const uint32_t* b) {
    asm volatile("mma.sync.aligned.m16n8k16.row.col.f32.f16.f16.f32 "
                 "{%0,%1,%2,%3}, {%4,%5,%6,%7}, {%8,%9}, {%0,%1,%2,%3};"
                 : "+f"(c[0]), "+f"(c[1]), "+f"(c[2]), "+f"(c[3])
                 : "r"(a[0]), "r"(a[1]), "r"(a[2]), "r"(a[3]), "r"(b[0]), "r"(b[1]));
}

// ================ fp16 single-pass NT GEMM ================
// C(MxN) = A(MxK) * B(NxK)^T, fp16 operands, fp32 accum.  K%64==0, M%256==0.
// CTA tile 256x128, 8 warps of 64x64, K-tile 64, 3-stage cp.async.
// smem/stage: A 256x128B = 32KB + B 128x128B = 16KB -> 48KB; 3 stages.
#define STAGE_B  49152
#define GSMEM_H  (3 * STAGE_B + 1024)

__global__ void __launch_bounds__(256, 1)
gemm_h(const __half* __restrict__ A, const __half* __restrict__ B,
       float* __restrict__ Cf, __half* __restrict__ Chf,
       int N, int K, int lda, int ldb, int ldc,
       long long sAb, long long sAh_, long long sBb, long long sBh_,
       long long sCb, long long sCh_, int Hdim, int mode)
{
    extern __shared__ char smraw[];
    const uint32_t sbase = (smem_u32(smraw) + 1023) & ~1023u;

    const int tid  = threadIdx.x;
    const int lane = tid & 31;
    const int warp = tid >> 5;
    const int wm = (warp >> 1) * 64;    // 4 warps in M
    const int wn = (warp & 1) * 64;     // 2 warps in N

    const int z  = blockIdx.z;
    const int zb = z / Hdim, zh = z - zb * Hdim;
    A += (long long)zb * sAb + (long long)zh * sAh_;
    B += (long long)zb * sBb + (long long)zh * sBh_;

    const int m0 = blockIdx.y * 256;
    const int n0 = blockIdx.x * 128;
    const int KT = K >> 6;

    // ---- producer mapping
    // A: thread owns full row (m0+tid): 8 chunks of 16B
    const __half* pA = A + (long long)(m0 + tid) * lda;
    uint32_t dOffA[8];
    #pragma unroll
    for (int c = 0; c < 8; c++)
        dOffA[c] = (uint32_t)(tid * 128 + ((c ^ (tid & 7)) << 4));
    // B: thread pair owns row (n0 + tid/2): 4 chunks each
    const int lrb = tid >> 1;
    const int lh  = tid & 1;
    const int brow = n0 + lrb;
    const uint32_t bsz = (brow < N) ? 16u : 0u;
    const __half* pB = B + (long long)((brow < N) ? brow : 0) * ldb;
    uint32_t dOffB[4];
    #pragma unroll
    for (int c2 = 0; c2 < 4; c2++)
        dOffB[c2] = (uint32_t)(32768 + lrb * 128 + ((((lh << 2) | c2) ^ (lrb & 7)) << 4));

    // ---- consumer (ldmatrix) per-lane bases
    const int rowA = wm + (lane & 15);
    const uint32_t aAoff = (uint32_t)rowA * 128;
    const int s4  = lane >> 4;
    const int e7A = rowA & 7;
    const int rowB = wn + ((lane >> 4) << 3) + (lane & 7);
    const uint32_t aBoff = 32768u + (uint32_t)rowB * 128;
    const int sB1 = (lane >> 3) & 1;
    const int e7B = lane & 7;

    float C[4][8][4];
    #pragma unroll
    for (int a = 0; a < 4; a++)
        #pragma unroll
        for (int b = 0; b < 8; b++)
            #pragma unroll
            for (int c = 0; c < 4; c++) C[a][b][c] = 0.f;

    // prologue: stages 0 and 1
    {
        #pragma unroll
        for (int c = 0; c < 8; c++) cpa16(sbase + dOffA[c], pA + c * 8, 16u);
        #pragma unroll
        for (int c2 = 0; c2 < 4; c2++)
            cpa16(sbase + dOffB[c2], pB + ((lh << 2) | c2) * 8, bsz);
        asm volatile("cp.async.commit_group;" ::: "memory");
        if (KT > 1) {
            #pragma unroll
            for (int c = 0; c < 8; c++) cpa16(sbase + STAGE_B + dOffA[c], pA + 64 + c * 8, 16u);
            #pragma unroll
            for (int c2 = 0; c2 < 4; c2++)
                cpa16(sbase + STAGE_B + dOffB[c2], pB + 64 + ((lh << 2) | c2) * 8, bsz);
            asm volatile("cp.async.commit_group;" ::: "memory");
        }
    }

    int s = 0;           // stage of tile t
    int sl = (KT >= 2) ? 2 : 0;   // stage to load next
    for (int t = 0; t < KT; t++) {
        if (t + 2 < KT) {
            asm volatile("cp.async.wait_group 1;" ::: "memory");
        } else {
            asm volatile("cp.async.wait_group 0;" ::: "memory");
        }
        __syncthreads();
        if (t + 2 < KT) {
            const uint32_t sa = sbase + (uint32_t)sl * STAGE_B;
            const int kb = (t + 2) << 6;
            #pragma unroll
            for (int c = 0; c < 8; c++) cpa16(sa + dOffA[c], pA + kb + c * 8, 16u);
            #pragma unroll
            for (int c2 = 0; c2 < 4; c2++)
                cpa16(sa + dOffB[c2], pB + kb + ((lh << 2) | c2) * 8, bsz);
            asm volatile("cp.async.commit_group;" ::: "memory");
            sl = (sl + 1 == 3) ? 0 : sl + 1;
        }
        const uint32_t st = sbase + (uint32_t)s * STAGE_B;
        s = (s + 1 == 3) ? 0 : s + 1;
        #pragma unroll
        for (int g = 0; g < 4; g++) {
            uint32_t Af[4][4];
            uint32_t Bf[8][2];
            const uint32_t posA = (uint32_t)((((g << 1) | s4) ^ e7A) << 4);
            #pragma unroll
            for (int mt = 0; mt < 4; mt++)
                ldm4(Af[mt], st + aAoff + mt * 2048u + posA);
            const uint32_t posB = (uint32_t)((((g << 1) | sB1) ^ e7B) << 4);
            #pragma unroll
            for (int ntp = 0; ntp < 4; ntp++) {
                uint32_t r[4];
                ldm4(r, st + aBoff + ntp * 2048u + posB);
                Bf[2 * ntp][0] = r[0]; Bf[2 * ntp][1] = r[1];
                Bf[2 * ntp + 1][0] = r[2]; Bf[2 * ntp + 1][1] = r[3];
            }
            #pragma unroll
            for (int mt = 0; mt < 4; mt++)
                #pragma unroll
                for (int nt = 0; nt < 8; nt++)
                    mma16816h(C[mt][nt], Af[mt], Bf[nt]);
        }
        __syncthreads();
    }

    // ---- epilogue
    const long long cz = (long long)zb * sCb + (long long)zh * sCh_;
    #pragma unroll
    for (int mt = 0; mt < 4; mt++) {
        const int rbase = m0 + wm + mt * 16 + (lane >> 2);
        #pragma unroll
        for (int i = 0; i < 2; i++) {
            const long long ro = (long long)(rbase + 8 * i) * ldc + cz;
            #pragma unroll
            for (int nt = 0; nt < 8; nt++) {
                const int col = n0 + wn + nt * 8 + ((lane & 3) << 1);
                if (col < N) {
                    const float v0 = C[mt][nt][2 * i];
                    const float v1 = C[mt][nt][2 * i + 1];
                    if (mode == 0) {
                        *reinterpret_cast<float2*>(Cf + ro + col) = make_float2(v0, v1);
                    } else {
                        *reinterpret_cast<__half2*>(Chf + ro + col) =
                            __floats2half2_rn(v0, v1);
                    }
                }
            }
        }
    }
}

// ---------------- elementwise / reduction kernels ----------------
__global__ void cvt_half_kernel(const float4* __restrict__ x,
                                __half2* __restrict__ y2, long long n4)
{
    long long i = (long long)blockIdx.x * 256 + threadIdx.x;
    if (i < n4) {
        float4 v = x[i];
        y2[2 * i]     = __floats2half2_rn(v.x, v.y);
        y2[2 * i + 1] = __floats2half2_rn(v.z, v.w);
    }
}

__device__ __forceinline__ float block_reduce(float v, float* red, bool is_max)
{
    #pragma unroll
    for (int o = 16; o > 0; o >>= 1) {
        float w = __shfl_xor_sync(0xffffffffu, v, o);
        v = is_max ? fmaxf(v, w) : (v + w);
    }
    if ((threadIdx.x & 31) == 0) red[threadIdx.x >> 5] = v;
    __syncthreads();
    float r = red[0];
    #pragma unroll
    for (int i = 1; i < 8; i++) r = is_max ? fmaxf(r, red[i]) : (r + red[i]);
    __syncthreads();
    return r;
}

// LN -> fp16 (strided out)
__global__ __launch_bounds__(256) void ln_half_kernel(
    const float* x, __half* y,
    const float* __restrict__ g, const float* __restrict__ b,
    int L, int ldx, int ldy)
{
    __shared__ float s[QLORA];
    __shared__ float red[8];
    long long row = blockIdx.x;
    const float* xr = x + row * ldx;
    size_t ybase = (size_t)row * ldy;
    int tid = threadIdx.x;

    float part = 0.f;
    for (int i = tid; i < L; i += 256) { float v = xr[i]; s[i] = v; part += v; }
    float mu = block_reduce(part, red, false) / (float)L;
    float p2 = 0.f;
    for (int i = tid; i < L; i += 256) { float d = s[i] - mu; p2 += d * d; }
    float var  = block_reduce(p2, red, false) / (float)L;
    float rstd = rsqrtf(var + 1e-5f);
    for (int i = tid; i < L; i += 256)
        y[ybase + i] = __float2half_rn((s[i] - mu) * rstd * g[i] + b[i]);
}

// softmax over SEQ rows -> fp16, vectorized IO
__global__ __launch_bounds__(256) void softmax_half_kernel(
    const float* __restrict__ sc, __half* __restrict__ pr, float scale)
{
    __shared__ float red[8];
    const float4* p4 = reinterpret_cast<const float4*>(sc + (long long)blockIdx.x * SEQ);
    size_t obase = (size_t)blockIdx.x * SEQ;
    int tid = threadIdx.x;
    float v[8];
    float4 a = p4[tid], b = p4[tid + 256];
    v[0]=a.x*scale; v[1]=a.y*scale; v[2]=a.z*scale; v[3]=a.w*scale;
    v[4]=b.x*scale; v[5]=b.y*scale; v[6]=b.z*scale; v[7]=b.w*scale;
    float mx = v[0];
    #pragma unroll
    for (int j = 1; j < 8; j++) mx = fmaxf(mx, v[j]);
    mx = block_reduce(mx, red, true);
    float sum = 0.f;
    #pragma unroll
    for (int j = 0; j < 8; j++) { v[j] = __expf(v[j] - mx); sum += v[j]; }
    sum = block_reduce(sum, red, false);
    float inv = 1.0f / sum;
    __half2* o2 = reinterpret_cast<__half2*>(pr + obase);
    #pragma unroll
    for (int j = 0; j < 2; j++) {
        int f4 = tid + j * 256;
        o2[2 * f4]     = __floats2half2_rn(v[4*j] * inv,   v[4*j+1] * inv);
        o2[2 * f4 + 1] = __floats2half2_rn(v[4*j+2] * inv, v[4*j+3] * inv);
    }
}

__global__ void rope_tab_kernel(const int* __restrict__ pos)
{
    int idx = blockIdx.x * blockDim.x + threadIdx.x;
    if (idx >= SEQ * 32) return;
    int s = idx >> 5, i = idx & 31;
    double freq = exp(-((double)(2 * i) / 64.0) * log(10000.0));
    double ang  = (double)pos[s] * freq;
    g_cos[idx] = (float)cos(ang);
    g_sin[idx] = (float)sin(ang);
}

// k_rope: kv_mixed f32 cols [512:576) -> kfull cols [512:576)
__global__ void rope_k_kernel()
{
    int idx = blockIdx.x * blockDim.x + threadIdx.x;
    if (idx >= T_TOK * 32) return;
    int t = idx >> 5, i = idx & 31;
    int s = t & (SEQ - 1);
    float c  = g_cos[(s << 5) + i];
    float sn = g_sin[(s << 5) + i];
    const float* x = g_kv_mixed + (size_t)t * CDIM + KVLORA;
    float x1 = x[i], x2 = x[i + 32];
    size_t o = (size_t)t * CDIM + KVLORA;
    g_kfull[o + i]      = __float2half_rn(x1 * c  - x2 * sn);
    g_kfull[o + i + 32] = __float2half_rn(x1 * sn + x2 * c);
}

// q_rope f32 -> qfull at [t, h*576+512 ...]
__global__ void rope_q_kernel()
{
    int idx = blockIdx.x * blockDim.x + threadIdx.x;
    if (idx >= T_TOK * NHEAD * 32) return;
    int t = idx >> 9;
    int rem = idx & 511;
    int h = rem >> 5, i = rem & 31;
    int s = t & (SEQ - 1);
    float c  = g_cos[(s << 5) + i];
    float sn = g_sin[(s << 5) + i];
    const float* x = g_q_rope + (size_t)t * (NHEAD * DR) + h * DR;
    float x1 = x[i], x2 = x[i + 32];
    size_t o = (size_t)t * QF_LD + h * CDIM + KVLORA;
    g_qfull[o + i]      = __float2half_rn(x1 * c  - x2 * sn);
    g_qfull[o + i + 32] = __float2half_rn(x1 * sn + x2 * c);
}

__global__ void transpose_kup_kernel(const float* __restrict__ w_kvb)
{
    int idx = blockIdx.x * blockDim.x + threadIdx.x;
    if (idx >= NHEAD * KVLORA * DN) return;
    int h   = idx >> 16;
    int rem = idx & 65535;
    int r   = rem >> 7;
    int d   = rem & 127;
    g_kupT[idx] = __float2half_rn(w_kvb[(size_t)((h << 7) + d) * KVLORA + r]);
}

// kvlatT[b][r][k] = kfull[(b*SEQ+k)*576 + r]
__global__ void transpose_kv_kernel()
{
    int idx = blockIdx.x * blockDim.x + threadIdx.x;
    if (idx >= BATCH * KVLORA * SEQ) return;
    int b   = idx >> 20;
    int rem = idx & ((1 << 20) - 1);
    int r   = rem >> 11;
    int k   = rem & (SEQ - 1);
    g_kvlatT[idx] = g_kfull[(size_t)((b << 11) + k) * CDIM + r];
}

// ---------------- host ----------------
extern "C" void kernel_launch(void* const* d_in, const int* in_sizes, int n_in,
                              void* d_out, int out_size)
{
    (void)in_sizes; (void)n_in; (void)out_size;
    const float* hidden   = (const float*)d_in[0];
    const float* w_qa     = (const float*)d_in[1];
    const float* ln_qa_g  = (const float*)d_in[2];
    const float* ln_qa_b  = (const float*)d_in[3];
    const float* w_qb     = (const float*)d_in[4];
    const float* w_qrope  = (const float*)d_in[5];
    const float* w_kva    = (const float*)d_in[6];
    const float* ln_kva_g = (const float*)d_in[7];
    const float* ln_kva_b = (const float*)d_in[8];
    const float* w_kvb    = (const float*)d_in[9];
    const float* w_o      = (const float*)d_in[10];
    const int*   pos      = (const int*)d_in[11];
    float* out = (float*)d_out;

    cudaFuncSetAttribute(gemm_h, cudaFuncAttributeMaxDynamicSharedMemorySize, GSMEM_H);

    float *q_mixed, *kv_mixed, *q_rope, *scores;
    __half *hid16,*wqa16,*wkva16,*wqb16,*wqr16,*wo16,*kupT16,*vup16;
    __half *qlat16,*qnope16,*qfull16,*kfull16,*kvlT16,*probs16,*attn16,*attnv16;
    cudaGetSymbolAddress((void**)&q_mixed, g_q_mixed);
    cudaGetSymbolAddress((void**)&kv_mixed, g_kv_mixed);
    cudaGetSymbolAddress((void**)&q_rope, g_q_rope);
    cudaGetSymbolAddress((void**)&scores, g_scores);
    cudaGetSymbolAddress((void**)&hid16, g_hidden);
    cudaGetSymbolAddress((void**)&wqa16, g_wqa);
    cudaGetSymbolAddress((void**)&wkva16, g_wkva);
    cudaGetSymbolAddress((void**)&wqb16, g_wqb);
    cudaGetSymbolAddress((void**)&wqr16, g_wqr);
    cudaGetSymbolAddress((void**)&wo16, g_wo);
    cudaGetSymbolAddress((void**)&kupT16, g_kupT);
    cudaGetSymbolAddress((void**)&vup16, g_vup);
    cudaGetSymbolAddress((void**)&qlat16, g_qlat);
    cudaGetSymbolAddress((void**)&qnope16, g_qnope);
    cudaGetSymbolAddress((void**)&qfull16, g_qfull);
    cudaGetSymbolAddress((void**)&kfull16, g_kfull);
    cudaGetSymbolAddress((void**)&kvlT16, g_kvlatT);
    cudaGetSymbolAddress((void**)&probs16, g_probs);
    cudaGetSymbolAddress((void**)&attn16, g_attn);
    cudaGetSymbolAddress((void**)&attnv16, g_attnv);

    auto cvt = [&](const float* x, __half* y, long long n) {
        long long n4 = n >> 2;
        cvt_half_kernel<<<(unsigned)((n4 + 255) / 256), 256>>>(
            (const float4*)x, (__half2*)y, n4);
    };
    auto gemmh = [&](const __half* Ap, const __half* Bp,
                     float* Cf, __half* Chf,
                     int M, int N, int K, int lda, int ldb, int ldc,
                     int Z, int Hdim,
                     long long sAb, long long sAh, long long sBb, long long sBh,
                     long long sCb, long long sCh, int mode) {
        dim3 grid((N + 127) / 128, M / 256, Z);
        gemm_h<<<grid, 256, GSMEM_H>>>(Ap, Bp, Cf, Chf,
                                       N, K, lda, ldb, ldc,
                                       sAb, sAh, sBb, sBh, sCb, sCh, Hdim, mode);
    };

    // operand conversions (fp16)
    cvt(hidden, hid16, (long long)T_TOK * DMODEL);
    cvt(w_qa,   wqa16, (long long)QLORA * DMODEL);
    cvt(w_kva,  wkva16, (long long)CDIM * DMODEL);
    cvt(w_qb,   wqb16, (long long)(NHEAD*DN) * QLORA);
    cvt(w_qrope,wqr16, (long long)(NHEAD*DR) * QLORA);
    cvt(w_o,    wo16,  (long long)DMODEL * (NHEAD*DV));
    cvt(w_kvb + (size_t)NHEAD * DN * KVLORA, vup16, (long long)NHEAD * DV * KVLORA);
    transpose_kup_kernel<<<(NHEAD * KVLORA * DN + 255) / 256, 256>>>(w_kvb);
    rope_tab_kernel<<<(SEQ * 32 + 255) / 256, 256>>>(pos);

    // 1. q_mixed = hidden @ w_qa^T ; LN -> qlat fp16
    gemmh(hid16, wqa16, q_mixed, nullptr,
          T_TOK, QLORA, DMODEL, DMODEL, DMODEL, QLORA, 1, 1, 0,0,0,0,0,0, 0);
    ln_half_kernel<<<T_TOK, 256>>>(q_mixed, qlat16, ln_qa_g, ln_qa_b, QLORA, QLORA, QLORA);

    // 2. kv_mixed = hidden @ w_kva^T ; LN -> kfull[:, :512] ; rope_k -> [:,512:]
    gemmh(hid16, wkva16, kv_mixed, nullptr,
          T_TOK, CDIM, DMODEL, DMODEL, DMODEL, CDIM, 1, 1, 0,0,0,0,0,0, 0);
    ln_half_kernel<<<T_TOK, 256>>>(kv_mixed, kfull16, ln_kva_g, ln_kva_b, KVLORA, CDIM, CDIM);
    rope_k_kernel<<<(T_TOK * 32 + 255) / 256, 256>>>();

    // 3. q_nope fp16 ; q_rope f32 -> rope_q -> qfull
    gemmh(qlat16, wqb16, nullptr, qnope16,
          T_TOK, NHEAD*DN, QLORA, QLORA, QLORA, NHEAD*DN, 1, 1, 0,0,0,0,0,0, 1);
    gemmh(qlat16, wqr16, q_rope, nullptr,
          T_TOK, NHEAD*DR, QLORA, QLORA, QLORA, NHEAD*DR, 1, 1, 0,0,0,0,0,0, 0);
    rope_q_kernel<<<(T_TOK * NHEAD * 32 + 255) / 256, 256>>>();

    // 4. absorb: qfull[:, h, :512] = q_nope_h @ kupT[h]^T  (fp16 out, strided)
    gemmh(qnope16, kupT16, nullptr, qfull16,
          T_TOK, KVLORA, DN, NHEAD*DN, DN, QF_LD, NHEAD, NHEAD,
          0, DN, 0, (long long)KVLORA * DN, 0, CDIM, 1);

    // 5. kvlatT
    transpose_kv_kernel<<<(BATCH * KVLORA * SEQ + 255) / 256, 256>>>();

    // 6. scores = qfull @ kfull^T  (f32 out)
    gemmh(qfull16, kfull16, scores, nullptr,
          SEQ, SEQ, CDIM, QF_LD, CDIM, SEQ, BATCH * NHEAD, NHEAD,
          (long long)SEQ * QF_LD, CDIM,
          (long long)SEQ * CDIM, 0,
          (long long)NHEAD * SEQ * SEQ, (long long)SEQ * SEQ, 0);

    // 7. softmax -> probs fp16
    float scale = (float)(1.0 / sqrt((double)(DN + DR)));
    softmax_half_kernel<<<BATCH * NHEAD * SEQ, 256>>>(scores, probs16, scale);

    // 8. attn = probs @ kvlatT^T  (fp16 out)
    gemmh(probs16, kvlT16, nullptr, attn16,
          SEQ, KVLORA, SEQ, SEQ, SEQ, KVLORA, BATCH * NHEAD, NHEAD,
          (long long)NHEAD * SEQ * SEQ, (long long)SEQ * SEQ,
          (long long)KVLORA * SEQ, 0,
          (long long)NHEAD * SEQ * KVLORA, (long long)SEQ * KVLORA, 1);

    // 9. attn_v = attn @ v_up^T  (fp16 out, strided into [b,s,h*DV])
    gemmh(attn16, vup16, nullptr, attnv16,
          SEQ, DV, KVLORA, KVLORA, KVLORA, NHEAD*DV, BATCH * NHEAD, NHEAD,
          (long long)NHEAD * SEQ * KVLORA, (long long)SEQ * KVLORA,
          0, (long long)DV * KVLORA,
          (long long)SEQ * (NHEAD*DV), DV, 1);

    // 10. out = attn_v @ w_o^T  (f32 out)
    gemmh(attnv16, wo16, out, nullptr,
          T_TOK, DMODEL, NHEAD*DV, NHEAD*DV, NHEAD*DV, DMODEL, 1, 1,
          0,0,0,0,0,0, 0);
}

// round 13
// speedup vs baseline: 1.2545x; 1.2545x over previous
#include <cuda_runtime.h>
#include <cuda_fp16.h>
#include <math.h>
#include <stdint.h>

// ---------------- problem constants ----------------
#define BATCH   2
#define SEQ     2048
#define T_TOK   4096
#define DMODEL  2048
#define NHEAD   16
#define QLORA   1536
#define KVLORA  512
#define DN      128
#define DR      64
#define DV      128
#define CDIM    576
#define QF_LD   (NHEAD*CDIM)   // 9216

// ---------------- scratch (static device memory) ----------------
__device__ float g_q_mixed [(size_t)T_TOK * QLORA];
__device__ float g_kv_mixed[(size_t)T_TOK * CDIM];
__device__ float g_q_rope  [(size_t)T_TOK * (NHEAD*DR)];
__device__ float g_scores  [(size_t)BATCH * NHEAD * SEQ * SEQ];

__device__ __half g_hidden [(size_t)T_TOK * DMODEL];
__device__ __half g_wqa    [(size_t)QLORA * DMODEL];
__device__ __half g_wkva   [(size_t)CDIM * DMODEL];
__device__ __half g_wqb    [(size_t)(NHEAD*DN) * QLORA];
__device__ __half g_wqr    [(size_t)(NHEAD*DR) * QLORA];
__device__ __half g_wo     [(size_t)DMODEL * (NHEAD*DV)];
__device__ __half g_kupT   [(size_t)NHEAD * KVLORA * DN];
__device__ __half g_vup    [(size_t)NHEAD * DV * KVLORA];
__device__ __half g_qlat   [(size_t)T_TOK * QLORA];
__device__ __half g_qnope  [(size_t)T_TOK * (NHEAD*DN)];
__device__ __half g_qfull  [(size_t)T_TOK * QF_LD];
__device__ __half g_kfull  [(size_t)T_TOK * CDIM];
__device__ __half g_kvlatT [(size_t)BATCH * KVLORA * SEQ];
__device__ __half g_probs  [(size_t)BATCH * NHEAD * SEQ * SEQ];
__device__ __half g_attn   [(size_t)BATCH * NHEAD * SEQ * KVLORA];
__device__ __half g_attnv  [(size_t)T_TOK * (NHEAD*DV)];

__device__ float g_cos[SEQ * 32];
__device__ float g_sin[SEQ * 32];

// ---------------- helpers ----------------
__device__ __forceinline__ uint32_t smem_u32(const void* p) {
    uint32_t a;
    asm("{ .reg .u64 t; cvta.to.shared.u64 t, %1; cvt.u32.u64 %0, t; }" : "=r"(a) : "l"(p));
    return a;
}
__device__ __forceinline__ void cpa16(uint32_t dst, const void* src, uint32_t sz) {
    asm volatile("cp.async.cg.shared.global [%0], [%1], 16, %2;"
                 :: "r"(dst), "l"(src), "r"(sz) : "memory");
}
__device__ __forceinline__ void ldm4(uint32_t* r, uint32_t a) {
    asm volatile("ldmatrix.sync.aligned.m8n8.x4.shared.b16 {%0,%1,%2,%3}, [%4];"
                 : "=r"(r[0]), "=r"(r[1]), "=r"(r[2]), "=r"(r[3]) : "r"(a));
}
__device__ __forceinline__ void mma16816h(float* c, const uint32_t* a, const uint32_t* b) {
    asm volatile("mma.sync.aligned.m16n8k16.row.col.f32.f16.f16.f32 "
                 "{%0,%1,%2,%3}, {%4,%5,%6,%7}, {%8,%9}, {%0,%1,%2,%3};"
                 : "+f"(c[0]), "+f"(c[1]), "+f"(c[2]), "+f"(c[3])
                 : "r"(a[0]), "r"(a[1]), "r"(a[2]), "r"(a[3]), "r"(b[0]), "r"(b[1]));
}

// ================ fp16 single-pass NT GEMM ================
// C(MxN) = A(MxK) * B(NxK)^T, fp16 operands, fp32 accum.  K%64==0, M%128==0.
// CTA tile 128x128, 8 warps of 64x32, K-tile 64, 3-stage cp.async, 2 CTAs/SM.
// smem/stage: A 128x128B = 16KB + B 128x128B = 16KB -> 32KB; 3 stages.
#define STAGE_B  32768
#define GSMEM_H  (3 * STAGE_B + 1024)

__global__ void __launch_bounds__(256, 2)
gemm_h(const __half* __restrict__ A, const __half* __restrict__ B,
       float* __restrict__ Cf, __half* __restrict__ Chf,
       int N, int K, int lda, int ldb, int ldc,
       long long sAb, long long sAh_, long long sBb, long long sBh_,
       long long sCb, long long sCh_, int Hdim, int mode)
{
    extern __shared__ char smraw[];
    const uint32_t sbase = (smem_u32(smraw) + 1023) & ~1023u;

    const int tid  = threadIdx.x;
    const int lane = tid & 31;
    const int warp = tid >> 5;
    const int wm = (warp >> 2) * 64;
    const int wn = (warp & 3) * 32;

    const int z  = blockIdx.z;
    const int zb = z / Hdim, zh = z - zb * Hdim;
    A += (long long)zb * sAb + (long long)zh * sAh_;
    B += (long long)zb * sBb + (long long)zh * sBh_;

    const int m0 = blockIdx.y * 128;
    const int n0 = blockIdx.x * 128;
    const int KT = K >> 6;

    // producer: 128B row = 64 halfs of contiguous K; thread covers 4 chunks
    const int lr = tid >> 1;
    const int lh = tid & 1;
    const __half* pA = A + (long long)(m0 + lr) * lda;
    const int brow = n0 + lr;
    const uint32_t bsz = (brow < N) ? 16u : 0u;
    const __half* pB = B + (long long)((brow < N) ? brow : 0) * ldb;
    uint32_t dOff[4];
    #pragma unroll
    for (int c2 = 0; c2 < 4; c2++)
        dOff[c2] = (uint32_t)(lr * 128 + ((((lh << 2) | c2) ^ (lr & 7)) << 4));

    const int rowA = wm + (lane & 15);
    const uint32_t aAoff = (uint32_t)rowA * 128;
    const int s4  = lane >> 4;
    const int e7A = rowA & 7;
    const int rowB = wn + ((lane >> 4) << 3) + (lane & 7);
    const uint32_t aBoff = 16384u + (uint32_t)rowB * 128;
    const int sB1 = (lane >> 3) & 1;
    const int e7B = lane & 7;

    float C[4][4][4];
    #pragma unroll
    for (int a = 0; a < 4; a++)
        #pragma unroll
        for (int b = 0; b < 4; b++)
            #pragma unroll
            for (int c = 0; c < 4; c++) C[a][b][c] = 0.f;

    // prologue: stage 0 (t=0) and stage 1 (t=1)
    {
        #pragma unroll
        for (int c2 = 0; c2 < 4; c2++) {
            cpa16(sbase + dOff[c2],          pA + ((lh << 2) | c2) * 8, 16u);
            cpa16(sbase + 16384u + dOff[c2], pB + ((lh << 2) | c2) * 8, bsz);
        }
        asm volatile("cp.async.commit_group;" ::: "memory");
        if (KT > 1) {
            #pragma unroll
            for (int c2 = 0; c2 < 4; c2++) {
                cpa16(sbase + STAGE_B + dOff[c2],          pA + 64 + ((lh << 2) | c2) * 8, 16u);
                cpa16(sbase + STAGE_B + 16384u + dOff[c2], pB + 64 + ((lh << 2) | c2) * 8, bsz);
            }
            asm volatile("cp.async.commit_group;" ::: "memory");
        }
    }

    int s = 0;                       // stage holding tile t
    int sl = (KT >= 2) ? 2 : 1;      // stage to receive tile t+2
    for (int t = 0; t < KT; t++) {
        if (t + 1 < KT) {
            asm volatile("cp.async.wait_group 1;" ::: "memory");
        } else {
            asm volatile("cp.async.wait_group 0;" ::: "memory");
        }
        __syncthreads();
        if (t + 2 < KT) {
            const uint32_t sa = sbase + (uint32_t)sl * STAGE_B;
            const int kb = (t + 2) << 6;
            #pragma unroll
            for (int c2 = 0; c2 < 4; c2++) {
                cpa16(sa + dOff[c2],          pA + kb + ((lh << 2) | c2) * 8, 16u);
                cpa16(sa + 16384u + dOff[c2], pB + kb + ((lh << 2) | c2) * 8, bsz);
            }
            asm volatile("cp.async.commit_group;" ::: "memory");
            sl = (sl + 1 == 3) ? 0 : sl + 1;
        }
        const uint32_t st = sbase + (uint32_t)s * STAGE_B;
        s = (s + 1 == 3) ? 0 : s + 1;
        #pragma unroll
        for (int g = 0; g < 4; g++) {
            uint32_t Af[4][4];
            uint32_t Bf[4][2];
            const uint32_t posA = (uint32_t)((((g << 1) | s4) ^ e7A) << 4);
            #pragma unroll
            for (int mt = 0; mt < 4; mt++)
                ldm4(Af[mt], st + aAoff + mt * 2048u + posA);
            const uint32_t posB = (uint32_t)((((g << 1) | sB1) ^ e7B) << 4);
            #pragma unroll
            for (int ntp = 0; ntp < 2; ntp++) {
                uint32_t r[4];
                ldm4(r, st + aBoff + ntp * 2048u + posB);
                Bf[2 * ntp][0] = r[0]; Bf[2 * ntp][1] = r[1];
                Bf[2 * ntp + 1][0] = r[2]; Bf[2 * ntp + 1][1] = r[3];
            }
            #pragma unroll
            for (int mt = 0; mt < 4; mt++)
                #pragma unroll
                for (int nt = 0; nt < 4; nt++)
                    mma16816h(C[mt][nt], Af[mt], Bf[nt]);
        }
        __syncthreads();
    }

    const long long cz = (long long)zb * sCb + (long long)zh * sCh_;
    #pragma unroll
    for (int mt = 0; mt < 4; mt++) {
        const int rbase = m0 + wm + mt * 16 + (lane >> 2);
        #pragma unroll
        for (int i = 0; i < 2; i++) {
            const long long ro = (long long)(rbase + 8 * i) * ldc + cz;
            #pragma unroll
            for (int nt = 0; nt < 4; nt++) {
                const int col = n0 + wn + nt * 8 + ((lane & 3) << 1);
                if (col < N) {
                    const float v0 = C[mt][nt][2 * i];
                    const float v1 = C[mt][nt][2 * i + 1];
                    if (mode == 0) {
                        *reinterpret_cast<float2*>(Cf + ro + col) = make_float2(v0, v1);
                    } else {
                        *reinterpret_cast<__half2*>(Chf + ro + col) =
                            __floats2half2_rn(v0, v1);
                    }
                }
            }
        }
    }
}

// ---------------- elementwise / reduction kernels ----------------
__global__ void cvt_half_kernel(const float4* __restrict__ x,
                                __half2* __restrict__ y2, long long n4)
{
    long long i = (long long)blockIdx.x * 256 + threadIdx.x;
    if (i < n4) {
        float4 v = x[i];
        y2[2 * i]     = __floats2half2_rn(v.x, v.y);
        y2[2 * i + 1] = __floats2half2_rn(v.z, v.w);
    }
}

__device__ __forceinline__ float block_reduce(float v, float* red, bool is_max)
{
    #pragma unroll
    for (int o = 16; o > 0; o >>= 1) {
        float w = __shfl_xor_sync(0xffffffffu, v, o);
        v = is_max ? fmaxf(v, w) : (v + w);
    }
    if ((threadIdx.x & 31) == 0) red[threadIdx.x >> 5] = v;
    __syncthreads();
    float r = red[0];
    #pragma unroll
    for (int i = 1; i < 8; i++) r = is_max ? fmaxf(r, red[i]) : (r + red[i]);
    __syncthreads();
    return r;
}

// LN -> fp16 (strided out)
__global__ __launch_bounds__(256) void ln_half_kernel(
    const float* x, __half* y,
    const float* __restrict__ g, const float* __restrict__ b,
    int L, int ldx, int ldy)
{
    __shared__ float s[QLORA];
    __shared__ float red[8];
    long long row = blockIdx.x;
    const float* xr = x + row * ldx;
    size_t ybase = (size_t)row * ldy;
    int tid = threadIdx.x;

    float part = 0.f;
    for (int i = tid; i < L; i += 256) { float v = xr[i]; s[i] = v; part += v; }
    float mu = block_reduce(part, red, false) / (float)L;
    float p2 = 0.f;
    for (int i = tid; i < L; i += 256) { float d = s[i] - mu; p2 += d * d; }
    float var  = block_reduce(p2, red, false) / (float)L;
    float rstd = rsqrtf(var + 1e-5f);
    for (int i = tid; i < L; i += 256)
        y[ybase + i] = __float2half_rn((s[i] - mu) * rstd * g[i] + b[i]);
}

// softmax over SEQ rows -> fp16, vectorized IO
__global__ __launch_bounds__(256) void softmax_half_kernel(
    const float* __restrict__ sc, __half* __restrict__ pr, float scale)
{
    __shared__ float red[8];
    const float4* p4 = reinterpret_cast<const float4*>(sc + (long long)blockIdx.x * SEQ);
    size_t obase = (size_t)blockIdx.x * SEQ;
    int tid = threadIdx.x;
    float v[8];
    float4 a = p4[tid], b = p4[tid + 256];
    v[0]=a.x*scale; v[1]=a.y*scale; v[2]=a.z*scale; v[3]=a.w*scale;
    v[4]=b.x*scale; v[5]=b.y*scale; v[6]=b.z*scale; v[7]=b.w*scale;
    float mx = v[0];
    #pragma unroll
    for (int j = 1; j < 8; j++) mx = fmaxf(mx, v[j]);
    mx = block_reduce(mx, red, true);
    float sum = 0.f;
    #pragma unroll
    for (int j = 0; j < 8; j++) { v[j] = __expf(v[j] - mx); sum += v[j]; }
    sum = block_reduce(sum, red, false);
    float inv = 1.0f / sum;
    __half2* o2 = reinterpret_cast<__half2*>(pr + obase);
    #pragma unroll
    for (int j = 0; j < 2; j++) {
        int f4 = tid + j * 256;
        o2[2 * f4]     = __floats2half2_rn(v[4*j] * inv,   v[4*j+1] * inv);
        o2[2 * f4 + 1] = __floats2half2_rn(v[4*j+2] * inv, v[4*j+3] * inv);
    }
}

__global__ void rope_tab_kernel(const int* __restrict__ pos)
{
    int idx = blockIdx.x * blockDim.x + threadIdx.x;
    if (idx >= SEQ * 32) return;
    int s = idx >> 5, i = idx & 31;
    double freq = exp(-((double)(2 * i) / 64.0) * log(10000.0));
    double ang  = (double)pos[s] * freq;
    g_cos[idx] = (float)cos(ang);
    g_sin[idx] = (float)sin(ang);
}

// k_rope: kv_mixed f32 cols [512:576) -> kfull cols [512:576)
__global__ void rope_k_kernel()
{
    int idx = blockIdx.x * blockDim.x + threadIdx.x;
    if (idx >= T_TOK * 32) return;
    int t = idx >> 5, i = idx & 31;
    int s = t & (SEQ - 1);
    float c  = g_cos[(s << 5) + i];
    float sn = g_sin[(s << 5) + i];
    const float* x = g_kv_mixed + (size_t)t * CDIM + KVLORA;
    float x1 = x[i], x2 = x[i + 32];
    size_t o = (size_t)t * CDIM + KVLORA;
    g_kfull[o + i]      = __float2half_rn(x1 * c  - x2 * sn);
    g_kfull[o + i + 32] = __float2half_rn(x1 * sn + x2 * c);
}

// q_rope f32 -> qfull at [t, h*576+512 ...]
__global__ void rope_q_kernel()
{
    int idx = blockIdx.x * blockDim.x + threadIdx.x;
    if (idx >= T_TOK * NHEAD * 32) return;
    int t = idx >> 9;
    int rem = idx & 511;
    int h = rem >> 5, i = rem & 31;
    int s = t & (SEQ - 1);
    float c  = g_cos[(s << 5) + i];
    float sn = g_sin[(s << 5) + i];
    const float* x = g_q_rope + (size_t)t * (NHEAD * DR) + h * DR;
    float x1 = x[i], x2 = x[i + 32];
    size_t o = (size_t)t * QF_LD + h * CDIM + KVLORA;
    g_qfull[o + i]      = __float2half_rn(x1 * c  - x2 * sn);
    g_qfull[o + i + 32] = __float2half_rn(x1 * sn + x2 * c);
}

__global__ void transpose_kup_kernel(const float* __restrict__ w_kvb)
{
    int idx = blockIdx.x * blockDim.x + threadIdx.x;
    if (idx >= NHEAD * KVLORA * DN) return;
    int h   = idx >> 16;
    int rem = idx & 65535;
    int r   = rem >> 7;
    int d   = rem & 127;
    g_kupT[idx] = __float2half_rn(w_kvb[(size_t)((h << 7) + d) * KVLORA + r]);
}

// kvlatT[b][r][k] = kfull[(b*SEQ+k)*576 + r]
__global__ void transpose_kv_kernel()
{
    int idx = blockIdx.x * blockDim.x + threadIdx.x;
    if (idx >= BATCH * KVLORA * SEQ) return;
    int b   = idx >> 20;
    int rem = idx & ((1 << 20) - 1);
    int r   = rem >> 11;
    int k   = rem & (SEQ - 1);
    g_kvlatT[idx] = g_kfull[(size_t)((b << 11) + k) * CDIM + r];
}

// ---------------- host ----------------
extern "C" void kernel_launch(void* const* d_in, const int* in_sizes, int n_in,
                              void* d_out, int out_size)
{
    (void)in_sizes; (void)n_in; (void)out_size;
    const float* hidden   = (const float*)d_in[0];
    const float* w_qa     = (const float*)d_in[1];
    const float* ln_qa_g  = (const float*)d_in[2];
    const float* ln_qa_b  = (const float*)d_in[3];
    const float* w_qb     = (const float*)d_in[4];
    const float* w_qrope  = (const float*)d_in[5];
    const float* w_kva    = (const float*)d_in[6];
    const float* ln_kva_g = (const float*)d_in[7];
    const float* ln_kva_b = (const float*)d_in[8];
    const float* w_kvb    = (const float*)d_in[9];
    const float* w_o      = (const float*)d_in[10];
    const int*   pos      = (const int*)d_in[11];
    float* out = (float*)d_out;

    cudaFuncSetAttribute(gemm_h, cudaFuncAttributeMaxDynamicSharedMemorySize, GSMEM_H);

    float *q_mixed, *kv_mixed, *q_rope, *scores;
    __half *hid16,*wqa16,*wkva16,*wqb16,*wqr16,*wo16,*kupT16,*vup16;
    __half *qlat16,*qnope16,*qfull16,*kfull16,*kvlT16,*probs16,*attn16,*attnv16;
    cudaGetSymbolAddress((void**)&q_mixed, g_q_mixed);
    cudaGetSymbolAddress((void**)&kv_mixed, g_kv_mixed);
    cudaGetSymbolAddress((void**)&q_rope, g_q_rope);
    cudaGetSymbolAddress((void**)&scores, g_scores);
    cudaGetSymbolAddress((void**)&hid16, g_hidden);
    cudaGetSymbolAddress((void**)&wqa16, g_wqa);
    cudaGetSymbolAddress((void**)&wkva16, g_wkva);
    cudaGetSymbolAddress((void**)&wqb16, g_wqb);
    cudaGetSymbolAddress((void**)&wqr16, g_wqr);
    cudaGetSymbolAddress((void**)&wo16, g_wo);
    cudaGetSymbolAddress((void**)&kupT16, g_kupT);
    cudaGetSymbolAddress((void**)&vup16, g_vup);
    cudaGetSymbolAddress((void**)&qlat16, g_qlat);
    cudaGetSymbolAddress((void**)&qnope16, g_qnope);
    cudaGetSymbolAddress((void**)&qfull16, g_qfull);
    cudaGetSymbolAddress((void**)&kfull16, g_kfull);
    cudaGetSymbolAddress((void**)&kvlT16, g_kvlatT);
    cudaGetSymbolAddress((void**)&probs16, g_probs);
    cudaGetSymbolAddress((void**)&attn16, g_attn);
    cudaGetSymbolAddress((void**)&attnv16, g_attnv);

    auto cvt = [&](const float* x, __half* y, long long n) {
        long long n4 = n >> 2;
        cvt_half_kernel<<<(unsigned)((n4 + 255) / 256), 256>>>(
            (const float4*)x, (__half2*)y, n4);
    };
    auto gemmh = [&](const __half* Ap, const __half* Bp,
                     float* Cf, __half* Chf,
                     int M, int N, int K, int lda, int ldb, int ldc,
                     int Z, int Hdim,
                     long long sAb, long long sAh, long long sBb, long long sBh,
                     long long sCb, long long sCh, int mode) {
        dim3 grid((N + 127) / 128, M / 128, Z);
        gemm_h<<<grid, 256, GSMEM_H>>>(Ap, Bp, Cf, Chf,
                                       N, K, lda, ldb, ldc,
                                       sAb, sAh, sBb, sBh, sCb, sCh, Hdim, mode);
    };

    // operand conversions (fp16)
    cvt(hidden, hid16, (long long)T_TOK * DMODEL);
    cvt(w_qa,   wqa16, (long long)QLORA * DMODEL);
    cvt(w_kva,  wkva16, (long long)CDIM * DMODEL);
    cvt(w_qb,   wqb16, (long long)(NHEAD*DN) * QLORA);
    cvt(w_qrope,wqr16, (long long)(NHEAD*DR) * QLORA);
    cvt(w_o,    wo16,  (long long)DMODEL * (NHEAD*DV));
    cvt(w_kvb + (size_t)NHEAD * DN * KVLORA, vup16, (long long)NHEAD * DV * KVLORA);
    transpose_kup_kernel<<<(NHEAD * KVLORA * DN + 255) / 256, 256>>>(w_kvb);
    rope_tab_kernel<<<(SEQ * 32 + 255) / 256, 256>>>(pos);

    // 1. q_mixed = hidden @ w_qa^T ; LN -> qlat fp16
    gemmh(hid16, wqa16, q_mixed, nullptr,
          T_TOK, QLORA, DMODEL, DMODEL, DMODEL, QLORA, 1, 1, 0,0,0,0,0,0, 0);
    ln_half_kernel<<<T_TOK, 256>>>(q_mixed, qlat16, ln_qa_g, ln_qa_b, QLORA, QLORA, QLORA);

    // 2. kv_mixed = hidden @ w_kva^T ; LN -> kfull[:, :512] ; rope_k -> [:,512:]
    gemmh(hid16, wkva16, kv_mixed, nullptr,
          T_TOK, CDIM, DMODEL, DMODEL, DMODEL, CDIM, 1, 1, 0,0,0,0,0,0, 0);
    ln_half_kernel<<<T_TOK, 256>>>(kv_mixed, kfull16, ln_kva_g, ln_kva_b, KVLORA, CDIM, CDIM);
    rope_k_kernel<<<(T_TOK * 32 + 255) / 256, 256>>>();

    // 3. q_nope fp16 ; q_rope f32 -> rope_q -> qfull
    gemmh(qlat16, wqb16, nullptr, qnope16,
          T_TOK, NHEAD*DN, QLORA, QLORA, QLORA, NHEAD*DN, 1, 1, 0,0,0,0,0,0, 1);
    gemmh(qlat16, wqr16, q_rope, nullptr,
          T_TOK, NHEAD*DR, QLORA, QLORA, QLORA, NHEAD*DR, 1, 1, 0,0,0,0,0,0, 0);
    rope_q_kernel<<<(T_TOK * NHEAD * 32 + 255) / 256, 256>>>();

    // 4. absorb: qfull[:, h, :512] = q_nope_h @ kupT[h]^T  (fp16 out, strided)
    gemmh(qnope16, kupT16, nullptr, qfull16,
          T_TOK, KVLORA, DN, NHEAD*DN, DN, QF_LD, NHEAD, NHEAD,
          0, DN, 0, (long long)KVLORA * DN, 0, CDIM, 1);

    // 5. kvlatT
    transpose_kv_kernel<<<(BATCH * KVLORA * SEQ + 255) / 256, 256>>>();

    // 6. scores = qfull @ kfull^T  (f32 out)
    gemmh(qfull16, kfull16, scores, nullptr,
          SEQ, SEQ, CDIM, QF_LD, CDIM, SEQ, BATCH * NHEAD, NHEAD,
          (long long)SEQ * QF_LD, CDIM,
          (long long)SEQ * CDIM, 0,
          (long long)NHEAD * SEQ * SEQ, (long long)SEQ * SEQ, 0);

    // 7. softmax -> probs fp16
    float scale = (float)(1.0 / sqrt((double)(DN + DR)));
    softmax_half_kernel<<<BATCH * NHEAD * SEQ, 256>>>(scores, probs16, scale);

    // 8. attn = probs @ kvlatT^T  (fp16 out)
    gemmh(probs16, kvlT16, nullptr, attn16,
          SEQ, KVLORA, SEQ, SEQ, SEQ, KVLORA, BATCH * NHEAD, NHEAD,
          (long long)NHEAD * SEQ * SEQ, (long long)SEQ * SEQ,
          (long long)KVLORA * SEQ, 0,
          (long long)NHEAD * SEQ * KVLORA, (long long)SEQ * KVLORA, 1);

    // 9. attn_v = attn @ v_up^T  (fp16 out, strided into [b,s,h*DV])
    gemmh(attn16, vup16, nullptr, attnv16,
          SEQ, DV, KVLORA, KVLORA, KVLORA, NHEAD*DV, BATCH * NHEAD, NHEAD,
          (long long)NHEAD * SEQ * KVLORA, (long long)SEQ * KVLORA,
          0, (long long)DV * KVLORA,
          (long long)SEQ * (NHEAD*DV), DV, 1);

    // 10. out = attn_v @ w_o^T  (f32 out)
    gemmh(attnv16, wo16, out, nullptr,
          T_TOK, DMODEL, NHEAD*DV, NHEAD*DV, NHEAD*DV, DMODEL, 1, 1,
          0,0,0,0,0,0, 0);
}

// round 14
// speedup vs baseline: 1.2831x; 1.0228x over previous
#include <cuda_runtime.h>
#include <cuda_fp16.h>
#include <math.h>
#include <stdint.h>

// ---------------- problem constants ----------------
#define BATCH   2
#define SEQ     2048
#define T_TOK   4096
#define DMODEL  2048
#define NHEAD   16
#define QLORA   1536
#define KVLORA  512
#define DN      128
#define DR      64
#define DV      128
#define CDIM    576
#define QF_LD   (NHEAD*CDIM)   // 9216

// ---------------- scratch (static device memory) ----------------
__device__ float g_q_mixed [(size_t)T_TOK * QLORA];
__device__ float g_kv_mixed[(size_t)T_TOK * CDIM];
__device__ float g_q_rope  [(size_t)T_TOK * (NHEAD*DR)];
__device__ float g_scores  [(size_t)BATCH * NHEAD * SEQ * SEQ];

__device__ __half g_hidden [(size_t)T_TOK * DMODEL];
__device__ __half g_wqa    [(size_t)QLORA * DMODEL];
__device__ __half g_wkva   [(size_t)CDIM * DMODEL];
__device__ __half g_wqb    [(size_t)(NHEAD*DN) * QLORA];
__device__ __half g_wqr    [(size_t)(NHEAD*DR) * QLORA];
__device__ __half g_wo     [(size_t)DMODEL * (NHEAD*DV)];
__device__ __half g_kupT   [(size_t)NHEAD * KVLORA * DN];
__device__ __half g_vup    [(size_t)NHEAD * DV * KVLORA];
__device__ __half g_qlat   [(size_t)T_TOK * QLORA];
__device__ __half g_qnope  [(size_t)T_TOK * (NHEAD*DN)];
__device__ __half g_qfull  [(size_t)T_TOK * QF_LD];
__device__ __half g_kfull  [(size_t)T_TOK * CDIM];
__device__ __half g_kvlatT [(size_t)BATCH * KVLORA * SEQ];
__device__ __half g_probs  [(size_t)BATCH * NHEAD * SEQ * SEQ];
__device__ __half g_attn   [(size_t)BATCH * NHEAD * SEQ * KVLORA];
__device__ __half g_attnv  [(size_t)T_TOK * (NHEAD*DV)];

__device__ float g_cos[SEQ * 32];
__device__ float g_sin[SEQ * 32];

// ---------------- helpers ----------------
__device__ __forceinline__ uint32_t smem_u32(const void* p) {
    uint32_t a;
    asm("{ .reg .u64 t; cvta.to.shared.u64 t, %1; cvt.u32.u64 %0, t; }" : "=r"(a) : "l"(p));
    return a;
}
__device__ __forceinline__ void cpa16(uint32_t dst, const void* src, uint32_t sz) {
    asm volatile("cp.async.cg.shared.global [%0], [%1], 16, %2;"
                 :: "r"(dst), "l"(src), "r"(sz) : "memory");
}
__device__ __forceinline__ void ldm4(uint32_t* r, uint32_t a) {
    asm volatile("ldmatrix.sync.aligned.m8n8.x4.shared.b16 {%0,%1,%2,%3}, [%4];"
                 : "=r"(r[0]), "=r"(r[1]), "=r"(r[2]), "=r"(r[3]) : "r"(a));
}
__device__ __forceinline__ void mma16816h(float* c, const uint32_t* a, const uint32_t* b) {
    asm volatile("mma.sync.aligned.m16n8k16.row.col.f32.f16.f16.f32 "
                 "{%0,%1,%2,%3}, {%4,%5,%6,%7}, {%8,%9}, {%0,%1,%2,%3};"
                 : "+f"(c[0]), "+f"(c[1]), "+f"(c[2]), "+f"(c[3])
                 : "r"(a[0]), "r"(a[1]), "r"(a[2]), "r"(a[3]), "r"(b[0]), "r"(b[1]));
}

// ================ fp16 single-pass NT GEMM ================
// C(MxN) = A(MxK) * B(NxK)^T, fp16 operands, fp32 accum.  K%64==0, M%128==0.
// CTA tile 128x128, 8 warps of 64x32, K-tile 64, 3-stage cp.async, 2 CTAs/SM.
// B-fragments double-buffered across k16 groups.
#define STAGE_B  32768
#define GSMEM_H  (3 * STAGE_B + 1024)

__global__ void __launch_bounds__(256, 2)
gemm_h(const __half* __restrict__ A, const __half* __restrict__ B,
       float* __restrict__ Cf, __half* __restrict__ Chf,
       int N, int K, int lda, int ldb, int ldc,
       long long sAb, long long sAh_, long long sBb, long long sBh_,
       long long sCb, long long sCh_, int Hdim, int mode)
{
    extern __shared__ char smraw[];
    const uint32_t sbase = (smem_u32(smraw) + 1023) & ~1023u;

    const int tid  = threadIdx.x;
    const int lane = tid & 31;
    const int warp = tid >> 5;
    const int wm = (warp >> 2) * 64;
    const int wn = (warp & 3) * 32;

    const int z  = blockIdx.z;
    const int zb = z / Hdim, zh = z - zb * Hdim;
    A += (long long)zb * sAb + (long long)zh * sAh_;
    B += (long long)zb * sBb + (long long)zh * sBh_;

    const int m0 = blockIdx.y * 128;
    const int n0 = blockIdx.x * 128;
    const int KT = K >> 6;

    // producer: 128B row = 64 halfs of contiguous K; thread covers 4 chunks
    const int lr = tid >> 1;
    const int lh = tid & 1;
    const __half* pA = A + (long long)(m0 + lr) * lda;
    const int brow = n0 + lr;
    const uint32_t bsz = (brow < N) ? 16u : 0u;
    const __half* pB = B + (long long)((brow < N) ? brow : 0) * ldb;
    uint32_t dOff[4];
    #pragma unroll
    for (int c2 = 0; c2 < 4; c2++)
        dOff[c2] = (uint32_t)(lr * 128 + ((((lh << 2) | c2) ^ (lr & 7)) << 4));

    const int rowA = wm + (lane & 15);
    const uint32_t aAoff = (uint32_t)rowA * 128;
    const int s4  = lane >> 4;
    const int e7A = rowA & 7;
    const int rowB = wn + ((lane >> 4) << 3) + (lane & 7);
    const uint32_t aBoff = 16384u + (uint32_t)rowB * 128;
    const int sB1 = (lane >> 3) & 1;
    const int e7B = lane & 7;

    float C[4][4][4];
    #pragma unroll
    for (int a = 0; a < 4; a++)
        #pragma unroll
        for (int b = 0; b < 4; b++)
            #pragma unroll
            for (int c = 0; c < 4; c++) C[a][b][c] = 0.f;

    // prologue: stage 0 (t=0) and stage 1 (t=1)
    {
        #pragma unroll
        for (int c2 = 0; c2 < 4; c2++) {
            cpa16(sbase + dOff[c2],          pA + ((lh << 2) | c2) * 8, 16u);
            cpa16(sbase + 16384u + dOff[c2], pB + ((lh << 2) | c2) * 8, bsz);
        }
        asm volatile("cp.async.commit_group;" ::: "memory");
        if (KT > 1) {
            #pragma unroll
            for (int c2 = 0; c2 < 4; c2++) {
                cpa16(sbase + STAGE_B + dOff[c2],          pA + 64 + ((lh << 2) | c2) * 8, 16u);
                cpa16(sbase + STAGE_B + 16384u + dOff[c2], pB + 64 + ((lh << 2) | c2) * 8, bsz);
            }
            asm volatile("cp.async.commit_group;" ::: "memory");
        }
    }

    int s = 0;                       // stage holding tile t
    int sl = (KT >= 2) ? 2 : 1;      // stage to receive tile t+2
    for (int t = 0; t < KT; t++) {
        if (t + 1 < KT) {
            asm volatile("cp.async.wait_group 1;" ::: "memory");
        } else {
            asm volatile("cp.async.wait_group 0;" ::: "memory");
        }
        __syncthreads();
        if (t + 2 < KT) {
            const uint32_t sa = sbase + (uint32_t)sl * STAGE_B;
            const int kb = (t + 2) << 6;
            #pragma unroll
            for (int c2 = 0; c2 < 4; c2++) {
                cpa16(sa + dOff[c2],          pA + kb + ((lh << 2) | c2) * 8, 16u);
                cpa16(sa + 16384u + dOff[c2], pB + kb + ((lh << 2) | c2) * 8, bsz);
            }
            asm volatile("cp.async.commit_group;" ::: "memory");
            sl = (sl + 1 == 3) ? 0 : sl + 1;
        }
        const uint32_t st = sbase + (uint32_t)s * STAGE_B;
        s = (s + 1 == 3) ? 0 : s + 1;

        // B-fragment double buffer: preload group 0
        uint32_t Bf[2][4][2];
        {
            const uint32_t posB = (uint32_t)((sB1 ^ e7B) << 4);
            #pragma unroll
            for (int ntp = 0; ntp < 2; ntp++) {
                uint32_t r[4];
                ldm4(r, st + aBoff + ntp * 2048u + posB);
                Bf[0][2 * ntp][0] = r[0]; Bf[0][2 * ntp][1] = r[1];
                Bf[0][2 * ntp + 1][0] = r[2]; Bf[0][2 * ntp + 1][1] = r[3];
            }
        }
        #pragma unroll
        for (int g = 0; g < 4; g++) {
            uint32_t Af[4][4];
            const uint32_t posA = (uint32_t)((((g << 1) | s4) ^ e7A) << 4);
            #pragma unroll
            for (int mt = 0; mt < 4; mt++)
                ldm4(Af[mt], st + aAoff + mt * 2048u + posA);
            if (g < 3) {
                const uint32_t posB = (uint32_t)(((((g + 1) << 1) | sB1) ^ e7B) << 4);
                #pragma unroll
                for (int ntp = 0; ntp < 2; ntp++) {
                    uint32_t r[4];
                    ldm4(r, st + aBoff + ntp * 2048u + posB);
                    Bf[(g + 1) & 1][2 * ntp][0] = r[0]; Bf[(g + 1) & 1][2 * ntp][1] = r[1];
                    Bf[(g + 1) & 1][2 * ntp + 1][0] = r[2]; Bf[(g + 1) & 1][2 * ntp + 1][1] = r[3];
                }
            }
            #pragma unroll
            for (int mt = 0; mt < 4; mt++)
                #pragma unroll
                for (int nt = 0; nt < 4; nt++)
                    mma16816h(C[mt][nt], Af[mt], Bf[g & 1][nt]);
        }
        __syncthreads();
    }

    const long long cz = (long long)zb * sCb + (long long)zh * sCh_;
    #pragma unroll
    for (int mt = 0; mt < 4; mt++) {
        const int rbase = m0 + wm + mt * 16 + (lane >> 2);
        #pragma unroll
        for (int i = 0; i < 2; i++) {
            const long long ro = (long long)(rbase + 8 * i) * ldc + cz;
            #pragma unroll
            for (int nt = 0; nt < 4; nt++) {
                const int col = n0 + wn + nt * 8 + ((lane & 3) << 1);
                if (col < N) {
                    const float v0 = C[mt][nt][2 * i];
                    const float v1 = C[mt][nt][2 * i + 1];
                    if (mode == 0) {
                        *reinterpret_cast<float2*>(Cf + ro + col) = make_float2(v0, v1);
                    } else {
                        *reinterpret_cast<__half2*>(Chf + ro + col) =
                            __floats2half2_rn(v0, v1);
                    }
                }
            }
        }
    }
}

// ---------------- elementwise / reduction kernels ----------------
__global__ void cvt_half_kernel(const float4* __restrict__ x,
                                __half2* __restrict__ y2, long long n4)
{
    long long i = (long long)blockIdx.x * 256 + threadIdx.x;
    if (i < n4) {
        float4 v = x[i];
        y2[2 * i]     = __floats2half2_rn(v.x, v.y);
        y2[2 * i + 1] = __floats2half2_rn(v.z, v.w);
    }
}

__device__ __forceinline__ float block_reduce(float v, float* red, bool is_max)
{
    #pragma unroll
    for (int o = 16; o > 0; o >>= 1) {
        float w = __shfl_xor_sync(0xffffffffu, v, o);
        v = is_max ? fmaxf(v, w) : (v + w);
    }
    if ((threadIdx.x & 31) == 0) red[threadIdx.x >> 5] = v;
    __syncthreads();
    float r = red[0];
    #pragma unroll
    for (int i = 1; i < 8; i++) r = is_max ? fmaxf(r, red[i]) : (r + red[i]);
    __syncthreads();
    return r;
}

// LN -> fp16 (strided out)
__global__ __launch_bounds__(256) void ln_half_kernel(
    const float* x, __half* y,
    const float* __restrict__ g, const float* __restrict__ b,
    int L, int ldx, int ldy)
{
    __shared__ float s[QLORA];
    __shared__ float red[8];
    long long row = blockIdx.x;
    const float* xr = x + row * ldx;
    size_t ybase = (size_t)row * ldy;
    int tid = threadIdx.x;

    float part = 0.f;
    for (int i = tid; i < L; i += 256) { float v = xr[i]; s[i] = v; part += v; }
    float mu = block_reduce(part, red, false) / (float)L;
    float p2 = 0.f;
    for (int i = tid; i < L; i += 256) { float d = s[i] - mu; p2 += d * d; }
    float var  = block_reduce(p2, red, false) / (float)L;
    float rstd = rsqrtf(var + 1e-5f);
    for (int i = tid; i < L; i += 256)
        y[ybase + i] = __float2half_rn((s[i] - mu) * rstd * g[i] + b[i]);
}

// softmax over SEQ rows -> fp16, vectorized IO
__global__ __launch_bounds__(256) void softmax_half_kernel(
    const float* __restrict__ sc, __half* __restrict__ pr, float scale)
{
    __shared__ float red[8];
    const float4* p4 = reinterpret_cast<const float4*>(sc + (long long)blockIdx.x * SEQ);
    size_t obase = (size_t)blockIdx.x * SEQ;
    int tid = threadIdx.x;
    float v[8];
    float4 a = p4[tid], b = p4[tid + 256];
    v[0]=a.x*scale; v[1]=a.y*scale; v[2]=a.z*scale; v[3]=a.w*scale;
    v[4]=b.x*scale; v[5]=b.y*scale; v[6]=b.z*scale; v[7]=b.w*scale;
    float mx = v[0];
    #pragma unroll
    for (int j = 1; j < 8; j++) mx = fmaxf(mx, v[j]);
    mx = block_reduce(mx, red, true);
    float sum = 0.f;
    #pragma unroll
    for (int j = 0; j < 8; j++) { v[j] = __expf(v[j] - mx); sum += v[j]; }
    sum = block_reduce(sum, red, false);
    float inv = 1.0f / sum;
    __half2* o2 = reinterpret_cast<__half2*>(pr + obase);
    #pragma unroll
    for (int j = 0; j < 2; j++) {
        int f4 = tid + j * 256;
        o2[2 * f4]     = __floats2half2_rn(v[4*j] * inv,   v[4*j+1] * inv);
        o2[2 * f4 + 1] = __floats2half2_rn(v[4*j+2] * inv, v[4*j+3] * inv);
    }
}

__global__ void rope_tab_kernel(const int* __restrict__ pos)
{
    int idx = blockIdx.x * blockDim.x + threadIdx.x;
    if (idx >= SEQ * 32) return;
    int s = idx >> 5, i = idx & 31;
    double freq = exp(-((double)(2 * i) / 64.0) * log(10000.0));
    double ang  = (double)pos[s] * freq;
    g_cos[idx] = (float)cos(ang);
    g_sin[idx] = (float)sin(ang);
}

// k_rope: kv_mixed f32 cols [512:576) -> kfull cols [512:576)
__global__ void rope_k_kernel()
{
    int idx = blockIdx.x * blockDim.x + threadIdx.x;
    if (idx >= T_TOK * 32) return;
    int t = idx >> 5, i = idx & 31;
    int s = t & (SEQ - 1);
    float c  = g_cos[(s << 5) + i];
    float sn = g_sin[(s << 5) + i];
    const float* x = g_kv_mixed + (size_t)t * CDIM + KVLORA;
    float x1 = x[i], x2 = x[i + 32];
    size_t o = (size_t)t * CDIM + KVLORA;
    g_kfull[o + i]      = __float2half_rn(x1 * c  - x2 * sn);
    g_kfull[o + i + 32] = __float2half_rn(x1 * sn + x2 * c);
}

// q_rope f32 -> qfull at [t, h*576+512 ...]
__global__ void rope_q_kernel()
{
    int idx = blockIdx.x * blockDim.x + threadIdx.x;
    if (idx >= T_TOK * NHEAD * 32) return;
    int t = idx >> 9;
    int rem = idx & 511;
    int h = rem >> 5, i = rem & 31;
    int s = t & (SEQ - 1);
    float c  = g_cos[(s << 5) + i];
    float sn = g_sin[(s << 5) + i];
    const float* x = g_q_rope + (size_t)t * (NHEAD * DR) + h * DR;
    float x1 = x[i], x2 = x[i + 32];
    size_t o = (size_t)t * QF_LD + h * CDIM + KVLORA;
    g_qfull[o + i]      = __float2half_rn(x1 * c  - x2 * sn);
    g_qfull[o + i + 32] = __float2half_rn(x1 * sn + x2 * c);
}

__global__ void transpose_kup_kernel(const float* __restrict__ w_kvb)
{
    int idx = blockIdx.x * blockDim.x + threadIdx.x;
    if (idx >= NHEAD * KVLORA * DN) return;
    int h   = idx >> 16;
    int rem = idx & 65535;
    int r   = rem >> 7;
    int d   = rem & 127;
    g_kupT[idx] = __float2half_rn(w_kvb[(size_t)((h << 7) + d) * KVLORA + r]);
}

// kvlatT[b][r][k] = kfull[(b*SEQ+k)*576 + r]
__global__ void transpose_kv_kernel()
{
    int idx = blockIdx.x * blockDim.x + threadIdx.x;
    if (idx >= BATCH * KVLORA * SEQ) return;
    int b   = idx >> 20;
    int rem = idx & ((1 << 20) - 1);
    int r   = rem >> 11;
    int k   = rem & (SEQ - 1);
    g_kvlatT[idx] = g_kfull[(size_t)((b << 11) + k) * CDIM + r];
}

// ---------------- host ----------------
extern "C" void kernel_launch(void* const* d_in, const int* in_sizes, int n_in,
                              void* d_out, int out_size)
{
    (void)in_sizes; (void)n_in; (void)out_size;
    const float* hidden   = (const float*)d_in[0];
    const float* w_qa     = (const float*)d_in[1];
    const float* ln_qa_g  = (const float*)d_in[2];
    const float* ln_qa_b  = (const float*)d_in[3];
    const float* w_qb     = (const float*)d_in[4];
    const float* w_qrope  = (const float*)d_in[5];
    const float* w_kva    = (const float*)d_in[6];
    const float* ln_kva_g = (const float*)d_in[7];
    const float* ln_kva_b = (const float*)d_in[8];
    const float* w_kvb    = (const float*)d_in[9];
    const float* w_o      = (const float*)d_in[10];
    const int*   pos      = (const int*)d_in[11];
    float* out = (float*)d_out;

    cudaFuncSetAttribute(gemm_h, cudaFuncAttributeMaxDynamicSharedMemorySize, GSMEM_H);

    float *q_mixed, *kv_mixed, *q_rope, *scores;
    __half *hid16,*wqa16,*wkva16,*wqb16,*wqr16,*wo16,*kupT16,*vup16;
    __half *qlat16,*qnope16,*qfull16,*kfull16,*kvlT16,*probs16,*attn16,*attnv16;
    cudaGetSymbolAddress((void**)&q_mixed, g_q_mixed);
    cudaGetSymbolAddress((void**)&kv_mixed, g_kv_mixed);
    cudaGetSymbolAddress((void**)&q_rope, g_q_rope);
    cudaGetSymbolAddress((void**)&scores, g_scores);
    cudaGetSymbolAddress((void**)&hid16, g_hidden);
    cudaGetSymbolAddress((void**)&wqa16, g_wqa);
    cudaGetSymbolAddress((void**)&wkva16, g_wkva);
    cudaGetSymbolAddress((void**)&wqb16, g_wqb);
    cudaGetSymbolAddress((void**)&wqr16, g_wqr);
    cudaGetSymbolAddress((void**)&wo16, g_wo);
    cudaGetSymbolAddress((void**)&kupT16, g_kupT);
    cudaGetSymbolAddress((void**)&vup16, g_vup);
    cudaGetSymbolAddress((void**)&qlat16, g_qlat);
    cudaGetSymbolAddress((void**)&qnope16, g_qnope);
    cudaGetSymbolAddress((void**)&qfull16, g_qfull);
    cudaGetSymbolAddress((void**)&kfull16, g_kfull);
    cudaGetSymbolAddress((void**)&kvlT16, g_kvlatT);
    cudaGetSymbolAddress((void**)&probs16, g_probs);
    cudaGetSymbolAddress((void**)&attn16, g_attn);
    cudaGetSymbolAddress((void**)&attnv16, g_attnv);

    auto cvt = [&](const float* x, __half* y, long long n) {
        long long n4 = n >> 2;
        cvt_half_kernel<<<(unsigned)((n4 + 255) / 256), 256>>>(
            (const float4*)x, (__half2*)y, n4);
    };
    auto gemmh = [&](const __half* Ap, const __half* Bp,
                     float* Cf, __half* Chf,
                     int M, int N, int K, int lda, int ldb, int ldc,
                     int Z, int Hdim,
                     long long sAb, long long sAh, long long sBb, long long sBh,
                     long long sCb, long long sCh, int mode) {
        dim3 grid((N + 127) / 128, M / 128, Z);
        gemm_h<<<grid, 256, GSMEM_H>>>(Ap, Bp, Cf, Chf,
                                       N, K, lda, ldb, ldc,
                                       sAb, sAh, sBb, sBh, sCb, sCh, Hdim, mode);
    };

    // ---- launches 1-5: conversions needed by gemm_qa (+ a few extra) ----
    cvt(hidden, hid16, (long long)T_TOK * DMODEL);          // 1
    cvt(w_qa,   wqa16, (long long)QLORA * DMODEL);          // 2
    cvt(w_kva,  wkva16, (long long)CDIM * DMODEL);          // 3
    cvt(w_qb,   wqb16, (long long)(NHEAD*DN) * QLORA);      // 4
    cvt(w_qrope,wqr16, (long long)(NHEAD*DR) * QLORA);      // 5

    // ---- launch 6: gemm_qa (this is what ncu -s 5 -c 1 profiles) ----
    gemmh(hid16, wqa16, q_mixed, nullptr,
          T_TOK, QLORA, DMODEL, DMODEL, DMODEL, QLORA, 1, 1, 0,0,0,0,0,0, 0);

    // ---- remaining conversions / setup ----
    cvt(w_o,    wo16,  (long long)DMODEL * (NHEAD*DV));
    cvt(w_kvb + (size_t)NHEAD * DN * KVLORA, vup16, (long long)NHEAD * DV * KVLORA);
    transpose_kup_kernel<<<(NHEAD * KVLORA * DN + 255) / 256, 256>>>(w_kvb);
    rope_tab_kernel<<<(SEQ * 32 + 255) / 256, 256>>>(pos);

    // 1b. LN -> qlat fp16
    ln_half_kernel<<<T_TOK, 256>>>(q_mixed, qlat16, ln_qa_g, ln_qa_b, QLORA, QLORA, QLORA);

    // 2. kv_mixed = hidden @ w_kva^T ; LN -> kfull[:, :512] ; rope_k -> [:,512:]
    gemmh(hid16, wkva16, kv_mixed, nullptr,
          T_TOK, CDIM, DMODEL, DMODEL, DMODEL, CDIM, 1, 1, 0,0,0,0,0,0, 0);
    ln_half_kernel<<<T_TOK, 256>>>(kv_mixed, kfull16, ln_kva_g, ln_kva_b, KVLORA, CDIM, CDIM);
    rope_k_kernel<<<(T_TOK * 32 + 255) / 256, 256>>>();

    // 3. q_nope fp16 ; q_rope f32 -> rope_q -> qfull
    gemmh(qlat16, wqb16, nullptr, qnope16,
          T_TOK, NHEAD*DN, QLORA, QLORA, QLORA, NHEAD*DN, 1, 1, 0,0,0,0,0,0, 1);
    gemmh(qlat16, wqr16, q_rope, nullptr,
          T_TOK, NHEAD*DR, QLORA, QLORA, QLORA, NHEAD*DR, 1, 1, 0,0,0,0,0,0, 0);
    rope_q_kernel<<<(T_TOK * NHEAD * 32 + 255) / 256, 256>>>();

    // 4. absorb: qfull[:, h, :512] = q_nope_h @ kupT[h]^T  (fp16 out, strided)
    gemmh(qnope16, kupT16, nullptr, qfull16,
          T_TOK, KVLORA, DN, NHEAD*DN, DN, QF_LD, NHEAD, NHEAD,
          0, DN, 0, (long long)KVLORA * DN, 0, CDIM, 1);

    // 5. kvlatT
    transpose_kv_kernel<<<(BATCH * KVLORA * SEQ + 255) / 256, 256>>>();

    // 6. scores = qfull @ kfull^T  (f32 out)
    gemmh(qfull16, kfull16, scores, nullptr,
          SEQ, SEQ, CDIM, QF_LD, CDIM, SEQ, BATCH * NHEAD, NHEAD,
          (long long)SEQ * QF_LD, CDIM,
          (long long)SEQ * CDIM, 0,
          (long long)NHEAD * SEQ * SEQ, (long long)SEQ * SEQ, 0);

    // 7. softmax -> probs fp16
    float scale = (float)(1.0 / sqrt((double)(DN + DR)));
    softmax_half_kernel<<<BATCH * NHEAD * SEQ, 256>>>(scores, probs16, scale);

    // 8. attn = probs @ kvlatT^T  (fp16 out)
    gemmh(probs16, kvlT16, nullptr, attn16,
          SEQ, KVLORA, SEQ, SEQ, SEQ, KVLORA, BATCH * NHEAD, NHEAD,
          (long long)NHEAD * SEQ * SEQ, (long long)SEQ * SEQ,
          (long long)KVLORA * SEQ, 0,
          (long long)NHEAD * SEQ * KVLORA, (long long)SEQ * KVLORA, 1);

    // 9. attn_v = attn @ v_up^T  (fp16 out, strided into [b,s,h*DV])
    gemmh(attn16, vup16, nullptr, attnv16,
          SEQ, DV, KVLORA, KVLORA, KVLORA, NHEAD*DV, BATCH * NHEAD, NHEAD,
          (long long)NHEAD * SEQ * KVLORA, (long long)SEQ * KVLORA,
          0, (long long)DV * KVLORA,
          (long long)SEQ * (NHEAD*DV), DV, 1);

    // 10. out = attn_v @ w_o^T  (f32 out)
    gemmh(attnv16, wo16, out, nullptr,
          T_TOK, DMODEL, NHEAD*DV, NHEAD*DV, NHEAD*DV, DMODEL, 1, 1,
          0,0,0,0,0,0, 0);
}

// round 15
// speedup vs baseline: 1.3097x; 1.0208x over previous
#include <cuda_runtime.h>
#include <cuda_fp16.h>
#include <math.h>
#include <stdint.h>

// ---------------- problem constants ----------------
#define BATCH   2
#define SEQ     2048
#define T_TOK   4096
#define DMODEL  2048
#define NHEAD   16
#define QLORA   1536
#define KVLORA  512
#define DN      128
#define DR      64
#define DV      128
#define CDIM    576
#define QF_LD   (NHEAD*CDIM)   // 9216
#define NCAT1   (QLORA + CDIM)     // 2112
#define NCAT2   (NHEAD*DN + NHEAD*DR)  // 3072

// ---------------- scratch (static device memory) ----------------
__device__ float  g_qkv_mixed[(size_t)T_TOK * NCAT1];   // qa | kva outputs
__device__ float  g_scores  [(size_t)BATCH * NHEAD * SEQ * SEQ];

__device__ __half g_hidden [(size_t)T_TOK * DMODEL];
__device__ __half g_wcat1  [(size_t)NCAT1 * DMODEL];    // wqa rows 0-1535, wkva 1536-2111
__device__ __half g_wcat2  [(size_t)NCAT2 * QLORA];     // wqb rows 0-2047, wqr 2048-3071
__device__ __half g_wo     [(size_t)DMODEL * (NHEAD*DV)];
__device__ __half g_kupT   [(size_t)NHEAD * KVLORA * DN];
__device__ __half g_vup    [(size_t)NHEAD * DV * KVLORA];
__device__ __half g_qlat   [(size_t)T_TOK * QLORA];
__device__ __half g_qcat   [(size_t)T_TOK * NCAT2];     // qnope cols 0-2047, qrope 2048-3071
__device__ __half g_qfull  [(size_t)T_TOK * QF_LD];
__device__ __half g_kfull  [(size_t)T_TOK * CDIM];
__device__ __half g_kvlatT [(size_t)BATCH * KVLORA * SEQ];
__device__ __half g_probs  [(size_t)BATCH * NHEAD * SEQ * SEQ];
__device__ __half g_attn   [(size_t)BATCH * NHEAD * SEQ * KVLORA];
__device__ __half g_attnv  [(size_t)T_TOK * (NHEAD*DV)];

__device__ float g_cos[SEQ * 32];
__device__ float g_sin[SEQ * 32];

// ---------------- helpers ----------------
__device__ __forceinline__ uint32_t smem_u32(const void* p) {
    uint32_t a;
    asm("{ .reg .u64 t; cvta.to.shared.u64 t, %1; cvt.u32.u64 %0, t; }" : "=r"(a) : "l"(p));
    return a;
}
__device__ __forceinline__ void cpa16(uint32_t dst, const void* src, uint32_t sz) {
    asm volatile("cp.async.cg.shared.global [%0], [%1], 16, %2;"
                 :: "r"(dst), "l"(src), "r"(sz) : "memory");
}
__device__ __forceinline__ void ldm4(uint32_t* r, uint32_t a) {
    asm volatile("ldmatrix.sync.aligned.m8n8.x4.shared.b16 {%0,%1,%2,%3}, [%4];"
                 : "=r"(r[0]), "=r"(r[1]), "=r"(r[2]), "=r"(r[3]) : "r"(a));
}
__device__ __forceinline__ void mma16816h(float* c, const uint32_t* a, const uint32_t* b) {
    asm volatile("mma.sync.aligned.m16n8k16.row.col.f32.f16.f16.f32 "
                 "{%0,%1,%2,%3}, {%4,%5,%6,%7}, {%8,%9}, {%0,%1,%2,%3};"
                 : "+f"(c[0]), "+f"(c[1]), "+f"(c[2]), "+f"(c[3])
                 : "r"(a[0]), "r"(a[1]), "r"(a[2]), "r"(a[3]), "r"(b[0]), "r"(b[1]));
}

// ================ fp16 single-pass NT GEMM ================
// C(MxN) = A(MxK) * B(NxK)^T, fp16 operands, fp32 accum.  K%64==0, M%128==0.
// CTA tile 128x128, 8 warps of 64x32, K-tile 64, 3-stage cp.async, 2 CTAs/SM.
// B-fragments double-buffered across k16 groups.
#define STAGE_B  32768
#define GSMEM_H  (3 * STAGE_B + 1024)

__global__ void __launch_bounds__(256, 2)
gemm_h(const __half* __restrict__ A, const __half* __restrict__ B,
       float* __restrict__ Cf, __half* __restrict__ Chf,
       int N, int K, int lda, int ldb, int ldc,
       long long sAb, long long sAh_, long long sBb, long long sBh_,
       long long sCb, long long sCh_, int Hdim, int mode)
{
    extern __shared__ char smraw[];
    const uint32_t sbase = (smem_u32(smraw) + 1023) & ~1023u;

    const int tid  = threadIdx.x;
    const int lane = tid & 31;
    const int warp = tid >> 5;
    const int wm = (warp >> 2) * 64;
    const int wn = (warp & 3) * 32;

    const int z  = blockIdx.z;
    const int zb = z / Hdim, zh = z - zb * Hdim;
    A += (long long)zb * sAb + (long long)zh * sAh_;
    B += (long long)zb * sBb + (long long)zh * sBh_;

    const int m0 = blockIdx.y * 128;
    const int n0 = blockIdx.x * 128;
    const int KT = K >> 6;

    // producer: 128B row = 64 halfs of contiguous K; thread covers 4 chunks
    const int lr = tid >> 1;
    const int lh = tid & 1;
    const __half* pA = A + (long long)(m0 + lr) * lda;
    const int brow = n0 + lr;
    const uint32_t bsz = (brow < N) ? 16u : 0u;
    const __half* pB = B + (long long)((brow < N) ? brow : 0) * ldb;
    uint32_t dOff[4];
    #pragma unroll
    for (int c2 = 0; c2 < 4; c2++)
        dOff[c2] = (uint32_t)(lr * 128 + ((((lh << 2) | c2) ^ (lr & 7)) << 4));

    const int rowA = wm + (lane & 15);
    const uint32_t aAoff = (uint32_t)rowA * 128;
    const int s4  = lane >> 4;
    const int e7A = rowA & 7;
    const int rowB = wn + ((lane >> 4) << 3) + (lane & 7);
    const uint32_t aBoff = 16384u + (uint32_t)rowB * 128;
    const int sB1 = (lane >> 3) & 1;
    const int e7B = lane & 7;

    float C[4][4][4];
    #pragma unroll
    for (int a = 0; a < 4; a++)
        #pragma unroll
        for (int b = 0; b < 4; b++)
            #pragma unroll
            for (int c = 0; c < 4; c++) C[a][b][c] = 0.f;

    // prologue: stage 0 (t=0) and stage 1 (t=1)
    {
        #pragma unroll
        for (int c2 = 0; c2 < 4; c2++) {
            cpa16(sbase + dOff[c2],          pA + ((lh << 2) | c2) * 8, 16u);
            cpa16(sbase + 16384u + dOff[c2], pB + ((lh << 2) | c2) * 8, bsz);
        }
        asm volatile("cp.async.commit_group;" ::: "memory");
        if (KT > 1) {
            #pragma unroll
            for (int c2 = 0; c2 < 4; c2++) {
                cpa16(sbase + STAGE_B + dOff[c2],          pA + 64 + ((lh << 2) | c2) * 8, 16u);
                cpa16(sbase + STAGE_B + 16384u + dOff[c2], pB + 64 + ((lh << 2) | c2) * 8, bsz);
            }
            asm volatile("cp.async.commit_group;" ::: "memory");
        }
    }

    int s = 0;                       // stage holding tile t
    int sl = (KT >= 2) ? 2 : 1;      // stage to receive tile t+2
    for (int t = 0; t < KT; t++) {
        if (t + 1 < KT) {
            asm volatile("cp.async.wait_group 1;" ::: "memory");
        } else {
            asm volatile("cp.async.wait_group 0;" ::: "memory");
        }
        __syncthreads();
        if (t + 2 < KT) {
            const uint32_t sa = sbase + (uint32_t)sl * STAGE_B;
            const int kb = (t + 2) << 6;
            #pragma unroll
            for (int c2 = 0; c2 < 4; c2++) {
                cpa16(sa + dOff[c2],          pA + kb + ((lh << 2) | c2) * 8, 16u);
                cpa16(sa + 16384u + dOff[c2], pB + kb + ((lh << 2) | c2) * 8, bsz);
            }
            asm volatile("cp.async.commit_group;" ::: "memory");
            sl = (sl + 1 == 3) ? 0 : sl + 1;
        }
        const uint32_t st = sbase + (uint32_t)s * STAGE_B;
        s = (s + 1 == 3) ? 0 : s + 1;

        // B-fragment double buffer: preload group 0
        uint32_t Bf[2][4][2];
        {
            const uint32_t posB = (uint32_t)((sB1 ^ e7B) << 4);
            #pragma unroll
            for (int ntp = 0; ntp < 2; ntp++) {
                uint32_t r[4];
                ldm4(r, st + aBoff + ntp * 2048u + posB);
                Bf[0][2 * ntp][0] = r[0]; Bf[0][2 * ntp][1] = r[1];
                Bf[0][2 * ntp + 1][0] = r[2]; Bf[0][2 * ntp + 1][1] = r[3];
            }
        }
        #pragma unroll
        for (int g = 0; g < 4; g++) {
            uint32_t Af[4][4];
            const uint32_t posA = (uint32_t)((((g << 1) | s4) ^ e7A) << 4);
            #pragma unroll
            for (int mt = 0; mt < 4; mt++)
                ldm4(Af[mt], st + aAoff + mt * 2048u + posA);
            if (g < 3) {
                const uint32_t posB = (uint32_t)(((((g + 1) << 1) | sB1) ^ e7B) << 4);
                #pragma unroll
                for (int ntp = 0; ntp < 2; ntp++) {
                    uint32_t r[4];
                    ldm4(r, st + aBoff + ntp * 2048u + posB);
                    Bf[(g + 1) & 1][2 * ntp][0] = r[0]; Bf[(g + 1) & 1][2 * ntp][1] = r[1];
                    Bf[(g + 1) & 1][2 * ntp + 1][0] = r[2]; Bf[(g + 1) & 1][2 * ntp + 1][1] = r[3];
                }
            }
            #pragma unroll
            for (int mt = 0; mt < 4; mt++)
                #pragma unroll
                for (int nt = 0; nt < 4; nt++)
                    mma16816h(C[mt][nt], Af[mt], Bf[g & 1][nt]);
        }
        __syncthreads();
    }

    const long long cz = (long long)zb * sCb + (long long)zh * sCh_;
    #pragma unroll
    for (int mt = 0; mt < 4; mt++) {
        const int rbase = m0 + wm + mt * 16 + (lane >> 2);
        #pragma unroll
        for (int i = 0; i < 2; i++) {
            const long long ro = (long long)(rbase + 8 * i) * ldc + cz;
            #pragma unroll
            for (int nt = 0; nt < 4; nt++) {
                const int col = n0 + wn + nt * 8 + ((lane & 3) << 1);
                if (col < N) {
                    const float v0 = C[mt][nt][2 * i];
                    const float v1 = C[mt][nt][2 * i + 1];
                    if (mode == 0) {
                        *reinterpret_cast<float2*>(Cf + ro + col) = make_float2(v0, v1);
                    } else {
                        *reinterpret_cast<__half2*>(Chf + ro + col) =
                            __floats2half2_rn(v0, v1);
                    }
                }
            }
        }
    }
}

// ---------------- elementwise / reduction kernels ----------------
__global__ void cvt_half_kernel(const float4* __restrict__ x,
                                __half2* __restrict__ y2, long long n4)
{
    long long i = (long long)blockIdx.x * 256 + threadIdx.x;
    if (i < n4) {
        float4 v = x[i];
        y2[2 * i]     = __floats2half2_rn(v.x, v.y);
        y2[2 * i + 1] = __floats2half2_rn(v.z, v.w);
    }
}

__device__ __forceinline__ float block_reduce(float v, float* red, bool is_max)
{
    #pragma unroll
    for (int o = 16; o > 0; o >>= 1) {
        float w = __shfl_xor_sync(0xffffffffu, v, o);
        v = is_max ? fmaxf(v, w) : (v + w);
    }
    if ((threadIdx.x & 31) == 0) red[threadIdx.x >> 5] = v;
    __syncthreads();
    float r = red[0];
    #pragma unroll
    for (int i = 1; i < 8; i++) r = is_max ? fmaxf(r, red[i]) : (r + red[i]);
    __syncthreads();
    return r;
}

// LN -> fp16 (strided in/out)
__global__ __launch_bounds__(256) void ln_half_kernel(
    const float* x, __half* y,
    const float* __restrict__ g, const float* __restrict__ b,
    int L, int ldx, int ldy)
{
    __shared__ float s[QLORA];
    __shared__ float red[8];
    long long row = blockIdx.x;
    const float* xr = x + row * ldx;
    size_t ybase = (size_t)row * ldy;
    int tid = threadIdx.x;

    float part = 0.f;
    for (int i = tid; i < L; i += 256) { float v = xr[i]; s[i] = v; part += v; }
    float mu = block_reduce(part, red, false) / (float)L;
    float p2 = 0.f;
    for (int i = tid; i < L; i += 256) { float d = s[i] - mu; p2 += d * d; }
    float var  = block_reduce(p2, red, false) / (float)L;
    float rstd = rsqrtf(var + 1e-5f);
    for (int i = tid; i < L; i += 256)
        y[ybase + i] = __float2half_rn((s[i] - mu) * rstd * g[i] + b[i]);
}

// softmax over SEQ rows -> fp16, vectorized IO
__global__ __launch_bounds__(256) void softmax_half_kernel(
    const float* __restrict__ sc, __half* __restrict__ pr, float scale)
{
    __shared__ float red[8];
    const float4* p4 = reinterpret_cast<const float4*>(sc + (long long)blockIdx.x * SEQ);
    size_t obase = (size_t)blockIdx.x * SEQ;
    int tid = threadIdx.x;
    float v[8];
    float4 a = p4[tid], b = p4[tid + 256];
    v[0]=a.x*scale; v[1]=a.y*scale; v[2]=a.z*scale; v[3]=a.w*scale;
    v[4]=b.x*scale; v[5]=b.y*scale; v[6]=b.z*scale; v[7]=b.w*scale;
    float mx = v[0];
    #pragma unroll
    for (int j = 1; j < 8; j++) mx = fmaxf(mx, v[j]);
    mx = block_reduce(mx, red, true);
    float sum = 0.f;
    #pragma unroll
    for (int j = 0; j < 8; j++) { v[j] = __expf(v[j] - mx); sum += v[j]; }
    sum = block_reduce(sum, red, false);
    float inv = 1.0f / sum;
    __half2* o2 = reinterpret_cast<__half2*>(pr + obase);
    #pragma unroll
    for (int j = 0; j < 2; j++) {
        int f4 = tid + j * 256;
        o2[2 * f4]     = __floats2half2_rn(v[4*j] * inv,   v[4*j+1] * inv);
        o2[2 * f4 + 1] = __floats2half2_rn(v[4*j+2] * inv, v[4*j+3] * inv);
    }
}

__global__ void rope_tab_kernel(const int* __restrict__ pos)
{
    int idx = blockIdx.x * blockDim.x + threadIdx.x;
    if (idx >= SEQ * 32) return;
    int s = idx >> 5, i = idx & 31;
    double freq = exp(-((double)(2 * i) / 64.0) * log(10000.0));
    double ang  = (double)pos[s] * freq;
    g_cos[idx] = (float)cos(ang);
    g_sin[idx] = (float)sin(ang);
}

// k_rope: qkv_mixed f32 cols [2048:2112) -> kfull cols [512:576)
__global__ void rope_k_kernel()
{
    int idx = blockIdx.x * blockDim.x + threadIdx.x;
    if (idx >= T_TOK * 32) return;
    int t = idx >> 5, i = idx & 31;
    int s = t & (SEQ - 1);
    float c  = g_cos[(s << 5) + i];
    float sn = g_sin[(s << 5) + i];
    const float* x = g_qkv_mixed + (size_t)t * NCAT1 + QLORA + KVLORA;
    float x1 = x[i], x2 = x[i + 32];
    size_t o = (size_t)t * CDIM + KVLORA;
    g_kfull[o + i]      = __float2half_rn(x1 * c  - x2 * sn);
    g_kfull[o + i + 32] = __float2half_rn(x1 * sn + x2 * c);
}

// q_rope: qcat fp16 cols [2048 + h*64 ...) -> qfull at [t, h*576+512 ...]
__global__ void rope_q_kernel()
{
    int idx = blockIdx.x * blockDim.x + threadIdx.x;
    if (idx >= T_TOK * NHEAD * 32) return;
    int t = idx >> 9;
    int rem = idx & 511;
    int h = rem >> 5, i = rem & 31;
    int s = t & (SEQ - 1);
    float c  = g_cos[(s << 5) + i];
    float sn = g_sin[(s << 5) + i];
    const __half* x = g_qcat + (size_t)t * NCAT2 + (NHEAD*DN) + h * DR;
    float x1 = __half2float(x[i]), x2 = __half2float(x[i + 32]);
    size_t o = (size_t)t * QF_LD + h * CDIM + KVLORA;
    g_qfull[o + i]      = __float2half_rn(x1 * c  - x2 * sn);
    g_qfull[o + i + 32] = __float2half_rn(x1 * sn + x2 * c);
}

__global__ void transpose_kup_kernel(const float* __restrict__ w_kvb)
{
    int idx = blockIdx.x * blockDim.x + threadIdx.x;
    if (idx >= NHEAD * KVLORA * DN) return;
    int h   = idx >> 16;
    int rem = idx & 65535;
    int r   = rem >> 7;
    int d   = rem & 127;
    g_kupT[idx] = __float2half_rn(w_kvb[(size_t)((h << 7) + d) * KVLORA + r]);
}

// kvlatT[b][r][k] = kfull[(b*SEQ+k)*576 + r]
__global__ void transpose_kv_kernel()
{
    int idx = blockIdx.x * blockDim.x + threadIdx.x;
    if (idx >= BATCH * KVLORA * SEQ) return;
    int b   = idx >> 20;
    int rem = idx & ((1 << 20) - 1);
    int r   = rem >> 11;
    int k   = rem & (SEQ - 1);
    g_kvlatT[idx] = g_kfull[(size_t)((b << 11) + k) * CDIM + r];
}

// ---------------- host ----------------
extern "C" void kernel_launch(void* const* d_in, const int* in_sizes, int n_in,
                              void* d_out, int out_size)
{
    (void)in_sizes; (void)n_in; (void)out_size;
    const float* hidden   = (const float*)d_in[0];
    const float* w_qa     = (const float*)d_in[1];
    const float* ln_qa_g  = (const float*)d_in[2];
    const float* ln_qa_b  = (const float*)d_in[3];
    const float* w_qb     = (const float*)d_in[4];
    const float* w_qrope  = (const float*)d_in[5];
    const float* w_kva    = (const float*)d_in[6];
    const float* ln_kva_g = (const float*)d_in[7];
    const float* ln_kva_b = (const float*)d_in[8];
    const float* w_kvb    = (const float*)d_in[9];
    const float* w_o      = (const float*)d_in[10];
    const int*   pos      = (const int*)d_in[11];
    float* out = (float*)d_out;

    cudaFuncSetAttribute(gemm_h, cudaFuncAttributeMaxDynamicSharedMemorySize, GSMEM_H);

    float *qkv_mixed, *scores;
    __half *hid16,*wcat1,*wcat2,*wo16,*kupT16,*vup16;
    __half *qlat16,*qcat16,*qfull16,*kfull16,*kvlT16,*probs16,*attn16,*attnv16;
    cudaGetSymbolAddress((void**)&qkv_mixed, g_qkv_mixed);
    cudaGetSymbolAddress((void**)&scores, g_scores);
    cudaGetSymbolAddress((void**)&hid16, g_hidden);
    cudaGetSymbolAddress((void**)&wcat1, g_wcat1);
    cudaGetSymbolAddress((void**)&wcat2, g_wcat2);
    cudaGetSymbolAddress((void**)&wo16, g_wo);
    cudaGetSymbolAddress((void**)&kupT16, g_kupT);
    cudaGetSymbolAddress((void**)&vup16, g_vup);
    cudaGetSymbolAddress((void**)&qlat16, g_qlat);
    cudaGetSymbolAddress((void**)&qcat16, g_qcat);
    cudaGetSymbolAddress((void**)&qfull16, g_qfull);
    cudaGetSymbolAddress((void**)&kfull16, g_kfull);
    cudaGetSymbolAddress((void**)&kvlT16, g_kvlatT);
    cudaGetSymbolAddress((void**)&probs16, g_probs);
    cudaGetSymbolAddress((void**)&attn16, g_attn);
    cudaGetSymbolAddress((void**)&attnv16, g_attnv);

    auto cvt = [&](const float* x, __half* y, long long n) {
        long long n4 = n >> 2;
        cvt_half_kernel<<<(unsigned)((n4 + 255) / 256), 256>>>(
            (const float4*)x, (__half2*)y, n4);
    };
    auto gemmh = [&](const __half* Ap, const __half* Bp,
                     float* Cf, __half* Chf,
                     int M, int N, int K, int lda, int ldb, int ldc,
                     int Z, int Hdim,
                     long long sAb, long long sAh, long long sBb, long long sBh,
                     long long sCb, long long sCh, int mode) {
        dim3 grid((N + 127) / 128, M / 128, Z);
        gemm_h<<<grid, 256, GSMEM_H>>>(Ap, Bp, Cf, Chf,
                                       N, K, lda, ldb, ldc,
                                       sAb, sAh, sBb, sBh, sCb, sCh, Hdim, mode);
    };

    // ---- launches 1-3: conversions for the fused qa|kva GEMM ----
    cvt(hidden, hid16, (long long)T_TOK * DMODEL);                        // 1
    cvt(w_qa,   wcat1, (long long)QLORA * DMODEL);                        // 2
    cvt(w_kva,  wcat1 + (size_t)QLORA * DMODEL, (long long)CDIM * DMODEL);// 3

    // ---- launch 4: fused qa|kva projection (ncu target) ----
    gemmh(hid16, wcat1, qkv_mixed, nullptr,
          T_TOK, NCAT1, DMODEL, DMODEL, DMODEL, NCAT1, 1, 1, 0,0,0,0,0,0, 0);

    // ---- remaining conversions / setup ----
    cvt(w_qb,   wcat2, (long long)(NHEAD*DN) * QLORA);
    cvt(w_qrope,wcat2 + (size_t)(NHEAD*DN) * QLORA, (long long)(NHEAD*DR) * QLORA);
    cvt(w_o,    wo16,  (long long)DMODEL * (NHEAD*DV));
    cvt(w_kvb + (size_t)NHEAD * DN * KVLORA, vup16, (long long)NHEAD * DV * KVLORA);
    transpose_kup_kernel<<<(NHEAD * KVLORA * DN + 255) / 256, 256>>>(w_kvb);
    rope_tab_kernel<<<(SEQ * 32 + 255) / 256, 256>>>(pos);

    // LN q (cols 0..1535) -> qlat ; LN kv (cols 1536..2047) -> kfull[:, :512] ; rope_k
    ln_half_kernel<<<T_TOK, 256>>>(qkv_mixed, qlat16, ln_qa_g, ln_qa_b, QLORA, NCAT1, QLORA);
    ln_half_kernel<<<T_TOK, 256>>>(qkv_mixed + QLORA, kfull16, ln_kva_g, ln_kva_b, KVLORA, NCAT1, CDIM);
    rope_k_kernel<<<(T_TOK * 32 + 255) / 256, 256>>>();

    // fused qnope|qrope -> qcat fp16 ; rope_q reads cols 2048+
    gemmh(qlat16, wcat2, nullptr, qcat16,
          T_TOK, NCAT2, QLORA, QLORA, QLORA, NCAT2, 1, 1, 0,0,0,0,0,0, 1);
    rope_q_kernel<<<(T_TOK * NHEAD * 32 + 255) / 256, 256>>>();

    // absorb: qfull[:, h, :512] = qcat[:, h*128:(h+1)*128] @ kupT[h]^T
    gemmh(qcat16, kupT16, nullptr, qfull16,
          T_TOK, KVLORA, DN, NCAT2, DN, QF_LD, NHEAD, NHEAD,
          0, DN, 0, (long long)KVLORA * DN, 0, CDIM, 1);

    // kvlatT
    transpose_kv_kernel<<<(BATCH * KVLORA * SEQ + 255) / 256, 256>>>();

    // scores = qfull @ kfull^T  (f32 out)
    gemmh(qfull16, kfull16, scores, nullptr,
          SEQ, SEQ, CDIM, QF_LD, CDIM, SEQ, BATCH * NHEAD, NHEAD,
          (long long)SEQ * QF_LD, CDIM,
          (long long)SEQ * CDIM, 0,
          (long long)NHEAD * SEQ * SEQ, (long long)SEQ * SEQ, 0);

    // softmax -> probs fp16
    float scale = (float)(1.0 / sqrt((double)(DN + DR)));
    softmax_half_kernel<<<BATCH * NHEAD * SEQ, 256>>>(scores, probs16, scale);

    // attn = probs @ kvlatT^T  (fp16 out)
    gemmh(probs16, kvlT16, nullptr, attn16,
          SEQ, KVLORA, SEQ, SEQ, SEQ, KVLORA, BATCH * NHEAD, NHEAD,
          (long long)NHEAD * SEQ * SEQ, (long long)SEQ * SEQ,
          (long long)KVLORA * SEQ, 0,
          (long long)NHEAD * SEQ * KVLORA, (long long)SEQ * KVLORA, 1);

    // attn_v = attn @ v_up^T  (fp16 out, strided into [b,s,h*DV])
    gemmh(attn16, vup16, nullptr, attnv16,
          SEQ, DV, KVLORA, KVLORA, KVLORA, NHEAD*DV, BATCH * NHEAD, NHEAD,
          (long long)NHEAD * SEQ * KVLORA, (long long)SEQ * KVLORA,
          0, (long long)DV * KVLORA,
          (long long)SEQ * (NHEAD*DV), DV, 1);

    // out = attn_v @ w_o^T  (f32 out)
    gemmh(attnv16, wo16, out, nullptr,
          T_TOK, DMODEL, NHEAD*DV, NHEAD*DV, NHEAD*DV, DMODEL, 1, 1,
          0,0,0,0,0,0, 0);
}

// round 16
// speedup vs baseline: 1.3268x; 1.0130x over previous
#include <cuda_runtime.h>
#include <cuda_fp16.h>
#include <math.h>
#include <stdint.h>

// ---------------- problem constants ----------------
#define BATCH   2
#define SEQ     2048
#define T_TOK   4096
#define DMODEL  2048
#define NHEAD   16
#define QLORA   1536
#define KVLORA  512
#define DN      128
#define DR      64
#define DV      128
#define CDIM    576
#define QF_LD   (NHEAD*CDIM)   // 9216
#define NCAT1   (QLORA + CDIM)     // 2112
#define NCAT2   (NHEAD*DN + NHEAD*DR)  // 3072

// ---------------- scratch (static device memory) ----------------
__device__ float  g_qkv_mixed[(size_t)T_TOK * NCAT1];   // qa | kva outputs
__device__ float  g_scores  [(size_t)BATCH * NHEAD * SEQ * SEQ];

__device__ __half g_hidden [(size_t)T_TOK * DMODEL];
__device__ __half g_wcat1  [(size_t)NCAT1 * DMODEL];    // wqa rows 0-1535, wkva 1536-2111
__device__ __half g_wcat2  [(size_t)NCAT2 * QLORA];     // wqb rows 0-2047, wqr 2048-3071
__device__ __half g_wo     [(size_t)DMODEL * (NHEAD*DV)];
__device__ __half g_kupT   [(size_t)NHEAD * KVLORA * DN];
__device__ __half g_vup    [(size_t)NHEAD * DV * KVLORA];
__device__ __half g_qlat   [(size_t)T_TOK * QLORA];
__device__ __half g_qcat   [(size_t)T_TOK * NCAT2];     // qnope cols 0-2047, qrope 2048-3071
__device__ __half g_qfull  [(size_t)T_TOK * QF_LD];
__device__ __half g_kfull  [(size_t)T_TOK * CDIM];
__device__ __half g_kvlatT [(size_t)BATCH * KVLORA * SEQ];
__device__ __half g_probs  [(size_t)BATCH * NHEAD * SEQ * SEQ];
__device__ __half g_attn   [(size_t)BATCH * NHEAD * SEQ * KVLORA];
__device__ __half g_attnv  [(size_t)T_TOK * (NHEAD*DV)];

__device__ float g_cos[SEQ * 32];
__device__ float g_sin[SEQ * 32];

// ---------------- helpers ----------------
__device__ __forceinline__ uint32_t smem_u32(const void* p) {
    uint32_t a;
    asm("{ .reg .u64 t; cvta.to.shared.u64 t, %1; cvt.u32.u64 %0, t; }" : "=r"(a) : "l"(p));
    return a;
}
__device__ __forceinline__ void cpa16(uint32_t dst, const void* src, uint32_t sz) {
    asm volatile("cp.async.cg.shared.global [%0], [%1], 16, %2;"
                 :: "r"(dst), "l"(src), "r"(sz) : "memory");
}
__device__ __forceinline__ void ldm4(uint32_t* r, uint32_t a) {
    asm volatile("ldmatrix.sync.aligned.m8n8.x4.shared.b16 {%0,%1,%2,%3}, [%4];"
                 : "=r"(r[0]), "=r"(r[1]), "=r"(r[2]), "=r"(r[3]) : "r"(a));
}
__device__ __forceinline__ void mma16816h(float* c, const uint32_t* a, const uint32_t* b) {
    asm volatile("mma.sync.aligned.m16n8k16.row.col.f32.f16.f16.f32 "
                 "{%0,%1,%2,%3}, {%4,%5,%6,%7}, {%8,%9}, {%0,%1,%2,%3};"
                 : "+f"(c[0]), "+f"(c[1]), "+f"(c[2]), "+f"(c[3])
                 : "r"(a[0]), "r"(a[1]), "r"(a[2]), "r"(a[3]), "r"(b[0]), "r"(b[1]));
}

// ================ fp16 single-pass NT GEMM ================
// C(MxN) = A(MxK) * B(NxK)^T, fp16 operands, fp32 accum.  K%64==0, M%128==0.
// CTA tile 128x128, 8 warps of 64x32, K-tile 64, 3-stage cp.async, 2 CTAs/SM.
// B-fragments double-buffered; single barrier per k-tile (3-stage invariant).
#define STAGE_B  32768
#define GSMEM_H  (3 * STAGE_B + 1024)

__global__ void __launch_bounds__(256, 2)
gemm_h(const __half* __restrict__ A, const __half* __restrict__ B,
       float* __restrict__ Cf, __half* __restrict__ Chf,
       int N, int K, int lda, int ldb, int ldc,
       long long sAb, long long sAh_, long long sBb, long long sBh_,
       long long sCb, long long sCh_, int Hdim, int mode)
{
    extern __shared__ char smraw[];
    const uint32_t sbase = (smem_u32(smraw) + 1023) & ~1023u;

    const int tid  = threadIdx.x;
    const int lane = tid & 31;
    const int warp = tid >> 5;
    const int wm = (warp >> 2) * 64;
    const int wn = (warp & 3) * 32;

    const int z  = blockIdx.z;
    const int zb = z / Hdim, zh = z - zb * Hdim;
    A += (long long)zb * sAb + (long long)zh * sAh_;
    B += (long long)zb * sBb + (long long)zh * sBh_;

    const int m0 = blockIdx.y * 128;
    const int n0 = blockIdx.x * 128;
    const int KT = K >> 6;

    // producer: 128B row = 64 halfs of contiguous K; thread covers 4 chunks
    const int lr = tid >> 1;
    const int lh = tid & 1;
    const __half* pA = A + (long long)(m0 + lr) * lda;
    const int brow = n0 + lr;
    const uint32_t bsz = (brow < N) ? 16u : 0u;
    const __half* pB = B + (long long)((brow < N) ? brow : 0) * ldb;
    uint32_t dOff[4];
    #pragma unroll
    for (int c2 = 0; c2 < 4; c2++)
        dOff[c2] = (uint32_t)(lr * 128 + ((((lh << 2) | c2) ^ (lr & 7)) << 4));

    const int rowA = wm + (lane & 15);
    const uint32_t aAoff = (uint32_t)rowA * 128;
    const int s4  = lane >> 4;
    const int e7A = rowA & 7;
    const int rowB = wn + ((lane >> 4) << 3) + (lane & 7);
    const uint32_t aBoff = 16384u + (uint32_t)rowB * 128;
    const int sB1 = (lane >> 3) & 1;
    const int e7B = lane & 7;

    float C[4][4][4];
    #pragma unroll
    for (int a = 0; a < 4; a++)
        #pragma unroll
        for (int b = 0; b < 4; b++)
            #pragma unroll
            for (int c = 0; c < 4; c++) C[a][b][c] = 0.f;

    // prologue: stage 0 (t=0) and stage 1 (t=1)
    {
        #pragma unroll
        for (int c2 = 0; c2 < 4; c2++) {
            cpa16(sbase + dOff[c2],          pA + ((lh << 2) | c2) * 8, 16u);
            cpa16(sbase + 16384u + dOff[c2], pB + ((lh << 2) | c2) * 8, bsz);
        }
        asm volatile("cp.async.commit_group;" ::: "memory");
        if (KT > 1) {
            #pragma unroll
            for (int c2 = 0; c2 < 4; c2++) {
                cpa16(sbase + STAGE_B + dOff[c2],          pA + 64 + ((lh << 2) | c2) * 8, 16u);
                cpa16(sbase + STAGE_B + 16384u + dOff[c2], pB + 64 + ((lh << 2) | c2) * 8, bsz);
            }
            asm volatile("cp.async.commit_group;" ::: "memory");
        }
    }

    int s = 0;                       // stage holding tile t
    int sl = (KT >= 2) ? 2 : 1;      // stage to receive tile t+2
    for (int t = 0; t < KT; t++) {
        if (t + 1 < KT) {
            asm volatile("cp.async.wait_group 1;" ::: "memory");
        } else {
            asm volatile("cp.async.wait_group 0;" ::: "memory");
        }
        __syncthreads();   // single barrier per iteration: orders stage reads
                           // of tile t-1 before its slot (t+2 mod 3) is refilled
        if (t + 2 < KT) {
            const uint32_t sa = sbase + (uint32_t)sl * STAGE_B;
            const int kb = (t + 2) << 6;
            #pragma unroll
            for (int c2 = 0; c2 < 4; c2++) {
                cpa16(sa + dOff[c2],          pA + kb + ((lh << 2) | c2) * 8, 16u);
                cpa16(sa + 16384u + dOff[c2], pB + kb + ((lh << 2) | c2) * 8, bsz);
            }
            asm volatile("cp.async.commit_group;" ::: "memory");
            sl = (sl + 1 == 3) ? 0 : sl + 1;
        }
        const uint32_t st = sbase + (uint32_t)s * STAGE_B;
        s = (s + 1 == 3) ? 0 : s + 1;

        // B-fragment double buffer: preload group 0
        uint32_t Bf[2][4][2];
        {
            const uint32_t posB = (uint32_t)((sB1 ^ e7B) << 4);
            #pragma unroll
            for (int ntp = 0; ntp < 2; ntp++) {
                uint32_t r[4];
                ldm4(r, st + aBoff + ntp * 2048u + posB);
                Bf[0][2 * ntp][0] = r[0]; Bf[0][2 * ntp][1] = r[1];
                Bf[0][2 * ntp + 1][0] = r[2]; Bf[0][2 * ntp + 1][1] = r[3];
            }
        }
        #pragma unroll
        for (int g = 0; g < 4; g++) {
            uint32_t Af[4][4];
            const uint32_t posA = (uint32_t)((((g << 1) | s4) ^ e7A) << 4);
            #pragma unroll
            for (int mt = 0; mt < 4; mt++)
                ldm4(Af[mt], st + aAoff + mt * 2048u + posA);
            if (g < 3) {
                const uint32_t posB = (uint32_t)(((((g + 1) << 1) | sB1) ^ e7B) << 4);
                #pragma unroll
                for (int ntp = 0; ntp < 2; ntp++) {
                    uint32_t r[4];
                    ldm4(r, st + aBoff + ntp * 2048u + posB);
                    Bf[(g + 1) & 1][2 * ntp][0] = r[0]; Bf[(g + 1) & 1][2 * ntp][1] = r[1];
                    Bf[(g + 1) & 1][2 * ntp + 1][0] = r[2]; Bf[(g + 1) & 1][2 * ntp + 1][1] = r[3];
                }
            }
            #pragma unroll
            for (int mt = 0; mt < 4; mt++)
                #pragma unroll
                for (int nt = 0; nt < 4; nt++)
                    mma16816h(C[mt][nt], Af[mt], Bf[g & 1][nt]);
        }
        // no trailing barrier: next iteration's top barrier provides ordering
    }

    const long long cz = (long long)zb * sCb + (long long)zh * sCh_;
    #pragma unroll
    for (int mt = 0; mt < 4; mt++) {
        const int rbase = m0 + wm + mt * 16 + (lane >> 2);
        #pragma unroll
        for (int i = 0; i < 2; i++) {
            const long long ro = (long long)(rbase + 8 * i) * ldc + cz;
            #pragma unroll
            for (int nt = 0; nt < 4; nt++) {
                const int col = n0 + wn + nt * 8 + ((lane & 3) << 1);
                if (col < N) {
                    const float v0 = C[mt][nt][2 * i];
                    const float v1 = C[mt][nt][2 * i + 1];
                    if (mode == 0) {
                        *reinterpret_cast<float2*>(Cf + ro + col) = make_float2(v0, v1);
                    } else {
                        *reinterpret_cast<__half2*>(Chf + ro + col) =
                            __floats2half2_rn(v0, v1);
                    }
                }
            }
        }
    }
}

// ---------------- elementwise / reduction kernels ----------------
__global__ void cvt_half_kernel(const float4* __restrict__ x,
                                __half2* __restrict__ y2, long long n4)
{
    long long i = (long long)blockIdx.x * 256 + threadIdx.x;
    if (i < n4) {
        float4 v = x[i];
        y2[2 * i]     = __floats2half2_rn(v.x, v.y);
        y2[2 * i + 1] = __floats2half2_rn(v.z, v.w);
    }
}

__device__ __forceinline__ float block_reduce(float v, float* red, bool is_max)
{
    #pragma unroll
    for (int o = 16; o > 0; o >>= 1) {
        float w = __shfl_xor_sync(0xffffffffu, v, o);
        v = is_max ? fmaxf(v, w) : (v + w);
    }
    if ((threadIdx.x & 31) == 0) red[threadIdx.x >> 5] = v;
    __syncthreads();
    float r = red[0];
    #pragma unroll
    for (int i = 1; i < 8; i++) r = is_max ? fmaxf(r, red[i]) : (r + red[i]);
    __syncthreads();
    return r;
}

// LN -> fp16 (strided in/out)
__global__ __launch_bounds__(256) void ln_half_kernel(
    const float* x, __half* y,
    const float* __restrict__ g, const float* __restrict__ b,
    int L, int ldx, int ldy)
{
    __shared__ float s[QLORA];
    __shared__ float red[8];
    long long row = blockIdx.x;
    const float* xr = x + row * ldx;
    size_t ybase = (size_t)row * ldy;
    int tid = threadIdx.x;

    float part = 0.f;
    for (int i = tid; i < L; i += 256) { float v = xr[i]; s[i] = v; part += v; }
    float mu = block_reduce(part, red, false) / (float)L;
    float p2 = 0.f;
    for (int i = tid; i < L; i += 256) { float d = s[i] - mu; p2 += d * d; }
    float var  = block_reduce(p2, red, false) / (float)L;
    float rstd = rsqrtf(var + 1e-5f);
    for (int i = tid; i < L; i += 256)
        y[ybase + i] = __float2half_rn((s[i] - mu) * rstd * g[i] + b[i]);
}

// softmax: one warp per SEQ row, shuffle-only reductions, 16 float4 in flight.
__global__ __launch_bounds__(256) void softmax_warp_kernel(
    const float* __restrict__ sc, __half* __restrict__ pr, float scale)
{
    const int wid  = threadIdx.x >> 5;
    const int lane = threadIdx.x & 31;
    const long long row = (long long)blockIdx.x * 8 + wid;
    const float4* p4 = reinterpret_cast<const float4*>(sc + row * SEQ);
    float v[64];
    #pragma unroll
    for (int j = 0; j < 16; j++) {
        float4 a = p4[lane + 32 * j];
        v[4*j+0] = a.x * scale; v[4*j+1] = a.y * scale;
        v[4*j+2] = a.z * scale; v[4*j+3] = a.w * scale;
    }
    float mx = v[0];
    #pragma unroll
    for (int j = 1; j < 64; j++) mx = fmaxf(mx, v[j]);
    #pragma unroll
    for (int o = 16; o > 0; o >>= 1) mx = fmaxf(mx, __shfl_xor_sync(0xffffffffu, mx, o));
    float sum = 0.f;
    #pragma unroll
    for (int j = 0; j < 64; j++) { v[j] = __expf(v[j] - mx); sum += v[j]; }
    #pragma unroll
    for (int o = 16; o > 0; o >>= 1) sum += __shfl_xor_sync(0xffffffffu, sum, o);
    const float inv = 1.0f / sum;
    __half2* o2 = reinterpret_cast<__half2*>(pr + row * SEQ);
    #pragma unroll
    for (int j = 0; j < 16; j++) {
        int f4 = lane + 32 * j;
        o2[2 * f4]     = __floats2half2_rn(v[4*j+0] * inv, v[4*j+1] * inv);
        o2[2 * f4 + 1] = __floats2half2_rn(v[4*j+2] * inv, v[4*j+3] * inv);
    }
}

__global__ void rope_tab_kernel(const int* __restrict__ pos)
{
    int idx = blockIdx.x * blockDim.x + threadIdx.x;
    if (idx >= SEQ * 32) return;
    int s = idx >> 5, i = idx & 31;
    double freq = exp(-((double)(2 * i) / 64.0) * log(10000.0));
    double ang  = (double)pos[s] * freq;
    g_cos[idx] = (float)cos(ang);
    g_sin[idx] = (float)sin(ang);
}

// k_rope: qkv_mixed f32 cols [2048:2112) -> kfull cols [512:576)
__global__ void rope_k_kernel()
{
    int idx = blockIdx.x * blockDim.x + threadIdx.x;
    if (idx >= T_TOK * 32) return;
    int t = idx >> 5, i = idx & 31;
    int s = t & (SEQ - 1);
    float c  = g_cos[(s << 5) + i];
    float sn = g_sin[(s << 5) + i];
    const float* x = g_qkv_mixed + (size_t)t * NCAT1 + QLORA + KVLORA;
    float x1 = x[i], x2 = x[i + 32];
    size_t o = (size_t)t * CDIM + KVLORA;
    g_kfull[o + i]      = __float2half_rn(x1 * c  - x2 * sn);
    g_kfull[o + i + 32] = __float2half_rn(x1 * sn + x2 * c);
}

// q_rope: qcat fp16 cols [2048 + h*64 ...) -> qfull at [t, h*576+512 ...]
__global__ void rope_q_kernel()
{
    int idx = blockIdx.x * blockDim.x + threadIdx.x;
    if (idx >= T_TOK * NHEAD * 32) return;
    int t = idx >> 9;
    int rem = idx & 511;
    int h = rem >> 5, i = rem & 31;
    int s = t & (SEQ - 1);
    float c  = g_cos[(s << 5) + i];
    float sn = g_sin[(s << 5) + i];
    const __half* x = g_qcat + (size_t)t * NCAT2 + (NHEAD*DN) + h * DR;
    float x1 = __half2float(x[i]), x2 = __half2float(x[i + 32]);
    size_t o = (size_t)t * QF_LD + h * CDIM + KVLORA;
    g_qfull[o + i]      = __float2half_rn(x1 * c  - x2 * sn);
    g_qfull[o + i + 32] = __float2half_rn(x1 * sn + x2 * c);
}

__global__ void transpose_kup_kernel(const float* __restrict__ w_kvb)
{
    int idx = blockIdx.x * blockDim.x + threadIdx.x;
    if (idx >= NHEAD * KVLORA * DN) return;
    int h   = idx >> 16;
    int rem = idx & 65535;
    int r   = rem >> 7;
    int d   = rem & 127;
    g_kupT[idx] = __float2half_rn(w_kvb[(size_t)((h << 7) + d) * KVLORA + r]);
}

// kvlatT[b][r][k] = kfull[(b*SEQ+k)*576 + r]
__global__ void transpose_kv_kernel()
{
    int idx = blockIdx.x * blockDim.x + threadIdx.x;
    if (idx >= BATCH * KVLORA * SEQ) return;
    int b   = idx >> 20;
    int rem = idx & ((1 << 20) - 1);
    int r   = rem >> 11;
    int k   = rem & (SEQ - 1);
    g_kvlatT[idx] = g_kfull[(size_t)((b << 11) + k) * CDIM + r];
}

// ---------------- host ----------------
extern "C" void kernel_launch(void* const* d_in, const int* in_sizes, int n_in,
                              void* d_out, int out_size)
{
    (void)in_sizes; (void)n_in; (void)out_size;
    const float* hidden   = (const float*)d_in[0];
    const float* w_qa     = (const float*)d_in[1];
    const float* ln_qa_g  = (const float*)d_in[2];
    const float* ln_qa_b  = (const float*)d_in[3];
    const float* w_qb     = (const float*)d_in[4];
    const float* w_qrope  = (const float*)d_in[5];
    const float* w_kva    = (const float*)d_in[6];
    const float* ln_kva_g = (const float*)d_in[7];
    const float* ln_kva_b = (const float*)d_in[8];
    const float* w_kvb    = (const float*)d_in[9];
    const float* w_o      = (const float*)d_in[10];
    const int*   pos      = (const int*)d_in[11];
    float* out = (float*)d_out;

    cudaFuncSetAttribute(gemm_h, cudaFuncAttributeMaxDynamicSharedMemorySize, GSMEM_H);

    float *qkv_mixed, *scores;
    __half *hid16,*wcat1,*wcat2,*wo16,*kupT16,*vup16;
    __half *qlat16,*qcat16,*qfull16,*kfull16,*kvlT16,*probs16,*attn16,*attnv16;
    cudaGetSymbolAddress((void**)&qkv_mixed, g_qkv_mixed);
    cudaGetSymbolAddress((void**)&scores, g_scores);
    cudaGetSymbolAddress((void**)&hid16, g_hidden);
    cudaGetSymbolAddress((void**)&wcat1, g_wcat1);
    cudaGetSymbolAddress((void**)&wcat2, g_wcat2);
    cudaGetSymbolAddress((void**)&wo16, g_wo);
    cudaGetSymbolAddress((void**)&kupT16, g_kupT);
    cudaGetSymbolAddress((void**)&vup16, g_vup);
    cudaGetSymbolAddress((void**)&qlat16, g_qlat);
    cudaGetSymbolAddress((void**)&qcat16, g_qcat);
    cudaGetSymbolAddress((void**)&qfull16, g_qfull);
    cudaGetSymbolAddress((void**)&kfull16, g_kfull);
    cudaGetSymbolAddress((void**)&kvlT16, g_kvlatT);
    cudaGetSymbolAddress((void**)&probs16, g_probs);
    cudaGetSymbolAddress((void**)&attn16, g_attn);
    cudaGetSymbolAddress((void**)&attnv16, g_attnv);

    auto cvt = [&](const float* x, __half* y, long long n) {
        long long n4 = n >> 2;
        cvt_half_kernel<<<(unsigned)((n4 + 255) / 256), 256>>>(
            (const float4*)x, (__half2*)y, n4);
    };
    auto gemmh = [&](const __half* Ap, const __half* Bp,
                     float* Cf, __half* Chf,
                     int M, int N, int K, int lda, int ldb, int ldc,
                     int Z, int Hdim,
                     long long sAb, long long sAh, long long sBb, long long sBh,
                     long long sCb, long long sCh, int mode) {
        dim3 grid((N + 127) / 128, M / 128, Z);
        gemm_h<<<grid, 256, GSMEM_H>>>(Ap, Bp, Cf, Chf,
                                       N, K, lda, ldb, ldc,
                                       sAb, sAh, sBb, sBh, sCb, sCh, Hdim, mode);
    };

    // ---- launches 1-3: conversions for the fused qa|kva GEMM ----
    cvt(hidden, hid16, (long long)T_TOK * DMODEL);                        // 1
    cvt(w_qa,   wcat1, (long long)QLORA * DMODEL);                        // 2
    cvt(w_kva,  wcat1 + (size_t)QLORA * DMODEL, (long long)CDIM * DMODEL);// 3

    // ---- launch 4: fused qa|kva projection (ncu target) ----
    gemmh(hid16, wcat1, qkv_mixed, nullptr,
          T_TOK, NCAT1, DMODEL, DMODEL, DMODEL, NCAT1, 1, 1, 0,0,0,0,0,0, 0);

    // ---- remaining conversions / setup ----
    cvt(w_qb,   wcat2, (long long)(NHEAD*DN) * QLORA);
    cvt(w_qrope,wcat2 + (size_t)(NHEAD*DN) * QLORA, (long long)(NHEAD*DR) * QLORA);
    cvt(w_o,    wo16,  (long long)DMODEL * (NHEAD*DV));
    cvt(w_kvb + (size_t)NHEAD * DN * KVLORA, vup16, (long long)NHEAD * DV * KVLORA);
    transpose_kup_kernel<<<(NHEAD * KVLORA * DN + 255) / 256, 256>>>(w_kvb);
    rope_tab_kernel<<<(SEQ * 32 + 255) / 256, 256>>>(pos);

    // LN q (cols 0..1535) -> qlat ; LN kv (cols 1536..2047) -> kfull[:, :512] ; rope_k
    ln_half_kernel<<<T_TOK, 256>>>(qkv_mixed, qlat16, ln_qa_g, ln_qa_b, QLORA, NCAT1, QLORA);
    ln_half_kernel<<<T_TOK, 256>>>(qkv_mixed + QLORA, kfull16, ln_kva_g, ln_kva_b, KVLORA, NCAT1, CDIM);
    rope_k_kernel<<<(T_TOK * 32 + 255) / 256, 256>>>();

    // fused qnope|qrope -> qcat fp16 ; rope_q reads cols 2048+
    gemmh(qlat16, wcat2, nullptr, qcat16,
          T_TOK, NCAT2, QLORA, QLORA, QLORA, NCAT2, 1, 1, 0,0,0,0,0,0, 1);
    rope_q_kernel<<<(T_TOK * NHEAD * 32 + 255) / 256, 256>>>();

    // absorb: qfull[:, h, :512] = qcat[:, h*128:(h+1)*128] @ kupT[h]^T
    gemmh(qcat16, kupT16, nullptr, qfull16,
          T_TOK, KVLORA, DN, NCAT2, DN, QF_LD, NHEAD, NHEAD,
          0, DN, 0, (long long)KVLORA * DN, 0, CDIM, 1);

    // kvlatT
    transpose_kv_kernel<<<(BATCH * KVLORA * SEQ + 255) / 256, 256>>>();

    // scores = qfull @ kfull^T  (f32 out)
    gemmh(qfull16, kfull16, scores, nullptr,
          SEQ, SEQ, CDIM, QF_LD, CDIM, SEQ, BATCH * NHEAD, NHEAD,
          (long long)SEQ * QF_LD, CDIM,
          (long long)SEQ * CDIM, 0,
          (long long)NHEAD * SEQ * SEQ, (long long)SEQ * SEQ, 0);

    // softmax -> probs fp16 (warp-per-row)
    float scale = (float)(1.0 / sqrt((double)(DN + DR)));
    softmax_warp_kernel<<<BATCH * NHEAD * SEQ / 8, 256>>>(scores, probs16, scale);

    // attn = probs @ kvlatT^T  (fp16 out)
    gemmh(probs16, kvlT16, nullptr, attn16,
          SEQ, KVLORA, SEQ, SEQ, SEQ, KVLORA, BATCH * NHEAD, NHEAD,
          (long long)NHEAD * SEQ * SEQ, (long long)SEQ * SEQ,
          (long long)KVLORA * SEQ, 0,
          (long long)NHEAD * SEQ * KVLORA, (long long)SEQ * KVLORA, 1);

    // attn_v = attn @ v_up^T  (fp16 out, strided into [b,s,h*DV])
    gemmh(attn16, vup16, nullptr, attnv16,
          SEQ, DV, KVLORA, KVLORA, KVLORA, NHEAD*DV, BATCH * NHEAD, NHEAD,
          (long long)NHEAD * SEQ * KVLORA, (long long)SEQ * KVLORA,
          0, (long long)DV * KVLORA,
          (long long)SEQ * (NHEAD*DV), DV, 1);

    // out = attn_v @ w_o^T  (f32 out)
    gemmh(attnv16, wo16, out, nullptr,
          T_TOK, DMODEL, NHEAD*DV, NHEAD*DV, NHEAD*DV, DMODEL, 1, 1,
          0,0,0,0,0,0, 0);
}

// round 17
// speedup vs baseline: 1.3796x; 1.0398x over previous
#include <cuda_runtime.h>
#include <cuda_fp16.h>
#include <math.h>
#include <stdint.h>

// ---------------- problem constants ----------------
#define BATCH   2
#define SEQ     2048
#define T_TOK   4096
#define DMODEL  2048
#define NHEAD   16
#define QLORA   1536
#define KVLORA  512
#define DN      128
#define DR      64
#define DV      128
#define CDIM    576
#define QF_LD   (NHEAD*CDIM)   // 9216
#define NCAT1   (QLORA + CDIM)     // 2112
#define NCAT2   (NHEAD*DN + NHEAD*DR)  // 3072

// ---------------- scratch (static device memory) ----------------
__device__ float  g_qkv_mixed[(size_t)T_TOK * NCAT1];   // qa | kva outputs
__device__ float  g_rsum    [(size_t)BATCH * NHEAD * SEQ];

__device__ __half g_hidden [(size_t)T_TOK * DMODEL];
__device__ __half g_wcat1  [(size_t)NCAT1 * DMODEL];    // wqa rows 0-1535, wkva 1536-2111
__device__ __half g_wcat2  [(size_t)NCAT2 * QLORA];     // wqb rows 0-2047, wqr 2048-3071
__device__ __half g_wo     [(size_t)DMODEL * (NHEAD*DV)];
__device__ __half g_kupT   [(size_t)NHEAD * KVLORA * DN];
__device__ __half g_vup    [(size_t)NHEAD * DV * KVLORA];
__device__ __half g_qlat   [(size_t)T_TOK * QLORA];
__device__ __half g_qcat   [(size_t)T_TOK * NCAT2];     // qnope cols 0-2047, qrope 2048-3071
__device__ __half g_qfull  [(size_t)T_TOK * QF_LD];
__device__ __half g_kfull  [(size_t)T_TOK * CDIM];
__device__ __half g_kvlatT [(size_t)BATCH * KVLORA * SEQ];
__device__ __half g_probs  [(size_t)BATCH * NHEAD * SEQ * SEQ];   // exp(scores), unnormalized
__device__ __half g_attn   [(size_t)BATCH * NHEAD * SEQ * KVLORA];
__device__ __half g_attnv  [(size_t)T_TOK * (NHEAD*DV)];

__device__ float g_cos[SEQ * 32];
__device__ float g_sin[SEQ * 32];

// ---------------- helpers ----------------
__device__ __forceinline__ uint32_t smem_u32(const void* p) {
    uint32_t a;
    asm("{ .reg .u64 t; cvta.to.shared.u64 t, %1; cvt.u32.u64 %0, t; }" : "=r"(a) : "l"(p));
    return a;
}
__device__ __forceinline__ void cpa16(uint32_t dst, const void* src, uint32_t sz) {
    asm volatile("cp.async.cg.shared.global [%0], [%1], 16, %2;"
                 :: "r"(dst), "l"(src), "r"(sz) : "memory");
}
__device__ __forceinline__ void ldm4(uint32_t* r, uint32_t a) {
    asm volatile("ldmatrix.sync.aligned.m8n8.x4.shared.b16 {%0,%1,%2,%3}, [%4];"
                 : "=r"(r[0]), "=r"(r[1]), "=r"(r[2]), "=r"(r[3]) : "r"(a));
}
__device__ __forceinline__ void mma16816h(float* c, const uint32_t* a, const uint32_t* b) {
    asm volatile("mma.sync.aligned.m16n8k16.row.col.f32.f16.f16.f32 "
                 "{%0,%1,%2,%3}, {%4,%5,%6,%7}, {%8,%9}, {%0,%1,%2,%3};"
                 : "+f"(c[0]), "+f"(c[1]), "+f"(c[2]), "+f"(c[3])
                 : "r"(a[0]), "r"(a[1]), "r"(a[2]), "r"(a[3]), "r"(b[0]), "r"(b[1]));
}

// ================ fp16 single-pass NT GEMM ================
// C(MxN) = A(MxK) * B(NxK)^T, fp16 operands, fp32 accum.  K%64==0, M%128==0.
// CTA tile 128x128, 8 warps of 64x32, K-tile 64, 3-stage cp.async, 2 CTAs/SM.
// modes: 0 = f32 out; 1 = fp16 out; 2 = fp16(exp(v*escale)) out;
//        3 = fp16(v / rs[z*SEQ + row]) out.
#define STAGE_B  32768
#define GSMEM_H  (3 * STAGE_B + 1024)

__global__ void __launch_bounds__(256, 2)
gemm_h(const __half* __restrict__ A, const __half* __restrict__ B,
       float* __restrict__ Cf, __half* __restrict__ Chf,
       const float* __restrict__ rs, float escale,
       int N, int K, int lda, int ldb, int ldc,
       long long sAb, long long sAh_, long long sBb, long long sBh_,
       long long sCb, long long sCh_, int Hdim, int mode)
{
    extern __shared__ char smraw[];
    const uint32_t sbase = (smem_u32(smraw) + 1023) & ~1023u;

    const int tid  = threadIdx.x;
    const int lane = tid & 31;
    const int warp = tid >> 5;
    const int wm = (warp >> 2) * 64;
    const int wn = (warp & 3) * 32;

    const int z  = blockIdx.z;
    const int zb = z / Hdim, zh = z - zb * Hdim;
    A += (long long)zb * sAb + (long long)zh * sAh_;
    B += (long long)zb * sBb + (long long)zh * sBh_;

    const int m0 = blockIdx.y * 128;
    const int n0 = blockIdx.x * 128;
    const int KT = K >> 6;

    // producer: 128B row = 64 halfs of contiguous K; thread covers 4 chunks
    const int lr = tid >> 1;
    const int lh = tid & 1;
    const __half* pA = A + (long long)(m0 + lr) * lda;
    const int brow = n0 + lr;
    const uint32_t bsz = (brow < N) ? 16u : 0u;
    const __half* pB = B + (long long)((brow < N) ? brow : 0) * ldb;
    uint32_t dOff[4];
    #pragma unroll
    for (int c2 = 0; c2 < 4; c2++)
        dOff[c2] = (uint32_t)(lr * 128 + ((((lh << 2) | c2) ^ (lr & 7)) << 4));

    const int rowA = wm + (lane & 15);
    const uint32_t aAoff = (uint32_t)rowA * 128;
    const int s4  = lane >> 4;
    const int e7A = rowA & 7;
    const int rowB = wn + ((lane >> 4) << 3) + (lane & 7);
    const uint32_t aBoff = 16384u + (uint32_t)rowB * 128;
    const int sB1 = (lane >> 3) & 1;
    const int e7B = lane & 7;

    float C[4][4][4];
    #pragma unroll
    for (int a = 0; a < 4; a++)
        #pragma unroll
        for (int b = 0; b < 4; b++)
            #pragma unroll
            for (int c = 0; c < 4; c++) C[a][b][c] = 0.f;

    // prologue: stage 0 (t=0) and stage 1 (t=1)
    {
        #pragma unroll
        for (int c2 = 0; c2 < 4; c2++) {
            cpa16(sbase + dOff[c2],          pA + ((lh << 2) | c2) * 8, 16u);
            cpa16(sbase + 16384u + dOff[c2], pB + ((lh << 2) | c2) * 8, bsz);
        }
        asm volatile("cp.async.commit_group;" ::: "memory");
        if (KT > 1) {
            #pragma unroll
            for (int c2 = 0; c2 < 4; c2++) {
                cpa16(sbase + STAGE_B + dOff[c2],          pA + 64 + ((lh << 2) | c2) * 8, 16u);
                cpa16(sbase + STAGE_B + 16384u + dOff[c2], pB + 64 + ((lh << 2) | c2) * 8, bsz);
            }
            asm volatile("cp.async.commit_group;" ::: "memory");
        }
    }

    int s = 0;                       // stage holding tile t
    int sl = (KT >= 2) ? 2 : 1;      // stage to receive tile t+2
    for (int t = 0; t < KT; t++) {
        if (t + 1 < KT) {
            asm volatile("cp.async.wait_group 1;" ::: "memory");
        } else {
            asm volatile("cp.async.wait_group 0;" ::: "memory");
        }
        __syncthreads();   // single barrier: orders tile t-1 reads before refill
        if (t + 2 < KT) {
            const uint32_t sa = sbase + (uint32_t)sl * STAGE_B;
            const int kb = (t + 2) << 6;
            #pragma unroll
            for (int c2 = 0; c2 < 4; c2++) {
                cpa16(sa + dOff[c2],          pA + kb + ((lh << 2) | c2) * 8, 16u);
                cpa16(sa + 16384u + dOff[c2], pB + kb + ((lh << 2) | c2) * 8, bsz);
            }
            asm volatile("cp.async.commit_group;" ::: "memory");
            sl = (sl + 1 == 3) ? 0 : sl + 1;
        }
        const uint32_t st = sbase + (uint32_t)s * STAGE_B;
        s = (s + 1 == 3) ? 0 : s + 1;

        // B-fragment double buffer: preload group 0
        uint32_t Bf[2][4][2];
        {
            const uint32_t posB = (uint32_t)((sB1 ^ e7B) << 4);
            #pragma unroll
            for (int ntp = 0; ntp < 2; ntp++) {
                uint32_t r[4];
                ldm4(r, st + aBoff + ntp * 2048u + posB);
                Bf[0][2 * ntp][0] = r[0]; Bf[0][2 * ntp][1] = r[1];
                Bf[0][2 * ntp + 1][0] = r[2]; Bf[0][2 * ntp + 1][1] = r[3];
            }
        }
        #pragma unroll
        for (int g = 0; g < 4; g++) {
            uint32_t Af[4][4];
            const uint32_t posA = (uint32_t)((((g << 1) | s4) ^ e7A) << 4);
            #pragma unroll
            for (int mt = 0; mt < 4; mt++)
                ldm4(Af[mt], st + aAoff + mt * 2048u + posA);
            if (g < 3) {
                const uint32_t posB = (uint32_t)(((((g + 1) << 1) | sB1) ^ e7B) << 4);
                #pragma unroll
                for (int ntp = 0; ntp < 2; ntp++) {
                    uint32_t r[4];
                    ldm4(r, st + aBoff + ntp * 2048u + posB);
                    Bf[(g + 1) & 1][2 * ntp][0] = r[0]; Bf[(g + 1) & 1][2 * ntp][1] = r[1];
                    Bf[(g + 1) & 1][2 * ntp + 1][0] = r[2]; Bf[(g + 1) & 1][2 * ntp + 1][1] = r[3];
                }
            }
            #pragma unroll
            for (int mt = 0; mt < 4; mt++)
                #pragma unroll
                for (int nt = 0; nt < 4; nt++)
                    mma16816h(C[mt][nt], Af[mt], Bf[g & 1][nt]);
        }
    }

    const long long cz = (long long)zb * sCb + (long long)zh * sCh_;
    #pragma unroll
    for (int mt = 0; mt < 4; mt++) {
        const int rbase = m0 + wm + mt * 16 + (lane >> 2);
        #pragma unroll
        for (int i = 0; i < 2; i++) {
            const int mrow = rbase + 8 * i;
            const long long ro = (long long)mrow * ldc + cz;
            float inv = 1.0f;
            if (mode == 3) inv = 1.0f / rs[(long long)z * SEQ + mrow];
            #pragma unroll
            for (int nt = 0; nt < 4; nt++) {
                const int col = n0 + wn + nt * 8 + ((lane & 3) << 1);
                if (col < N) {
                    float v0 = C[mt][nt][2 * i];
                    float v1 = C[mt][nt][2 * i + 1];
                    if (mode == 0) {
                        *reinterpret_cast<float2*>(Cf + ro + col) = make_float2(v0, v1);
                    } else {
                        if (mode == 2) {
                            v0 = __expf(v0 * escale);
                            v1 = __expf(v1 * escale);
                        } else if (mode == 3) {
                            v0 *= inv; v1 *= inv;
                        }
                        *reinterpret_cast<__half2*>(Chf + ro + col) =
                            __floats2half2_rn(v0, v1);
                    }
                }
            }
        }
    }
}

// ---------------- elementwise / reduction kernels ----------------
__global__ void cvt_half_kernel(const float4* __restrict__ x,
                                __half2* __restrict__ y2, long long n4)
{
    long long i = (long long)blockIdx.x * 256 + threadIdx.x;
    if (i < n4) {
        float4 v = x[i];
        y2[2 * i]     = __floats2half2_rn(v.x, v.y);
        y2[2 * i + 1] = __floats2half2_rn(v.z, v.w);
    }
}

__device__ __forceinline__ float block_reduce(float v, float* red, bool is_max)
{
    #pragma unroll
    for (int o = 16; o > 0; o >>= 1) {
        float w = __shfl_xor_sync(0xffffffffu, v, o);
        v = is_max ? fmaxf(v, w) : (v + w);
    }
    if ((threadIdx.x & 31) == 0) red[threadIdx.x >> 5] = v;
    __syncthreads();
    float r = red[0];
    #pragma unroll
    for (int i = 1; i < 8; i++) r = is_max ? fmaxf(r, red[i]) : (r + red[i]);
    __syncthreads();
    return r;
}

// LN -> fp16 (strided in/out)
__global__ __launch_bounds__(256) void ln_half_kernel(
    const float* x, __half* y,
    const float* __restrict__ g, const float* __restrict__ b,
    int L, int ldx, int ldy)
{
    __shared__ float s[QLORA];
    __shared__ float red[8];
    long long row = blockIdx.x;
    const float* xr = x + row * ldx;
    size_t ybase = (size_t)row * ldy;
    int tid = threadIdx.x;

    float part = 0.f;
    for (int i = tid; i < L; i += 256) { float v = xr[i]; s[i] = v; part += v; }
    float mu = block_reduce(part, red, false) / (float)L;
    float p2 = 0.f;
    for (int i = tid; i < L; i += 256) { float d = s[i] - mu; p2 += d * d; }
    float var  = block_reduce(p2, red, false) / (float)L;
    float rstd = rsqrtf(var + 1e-5f);
    for (int i = tid; i < L; i += 256)
        y[ybase + i] = __float2half_rn((s[i] - mu) * rstd * g[i] + b[i]);
}

// row sums of fp16 probs: one warp per SEQ row
__global__ __launch_bounds__(256) void rowsum_kernel(
    const __half* __restrict__ pr, float* __restrict__ rs)
{
    const int wid  = threadIdx.x >> 5;
    const int lane = threadIdx.x & 31;
    const long long row = (long long)blockIdx.x * 8 + wid;
    const uint4* p = reinterpret_cast<const uint4*>(pr + row * SEQ);
    float sum = 0.f;
    #pragma unroll
    for (int j = 0; j < 8; j++) {
        uint4 a = p[lane + 32 * j];
        const __half2* h = reinterpret_cast<const __half2*>(&a);
        #pragma unroll
        for (int q = 0; q < 4; q++) {
            float2 f = __half22float2(h[q]);
            sum += f.x + f.y;
        }
    }
    #pragma unroll
    for (int o = 16; o > 0; o >>= 1) sum += __shfl_xor_sync(0xffffffffu, sum, o);
    if (lane == 0) rs[row] = sum;
}

__global__ void rope_tab_kernel(const int* __restrict__ pos)
{
    int idx = blockIdx.x * blockDim.x + threadIdx.x;
    if (idx >= SEQ * 32) return;
    int s = idx >> 5, i = idx & 31;
    double freq = exp(-((double)(2 * i) / 64.0) * log(10000.0));
    double ang  = (double)pos[s] * freq;
    g_cos[idx] = (float)cos(ang);
    g_sin[idx] = (float)sin(ang);
}

// k_rope: qkv_mixed f32 cols [2048:2112) -> kfull cols [512:576)
__global__ void rope_k_kernel()
{
    int idx = blockIdx.x * blockDim.x + threadIdx.x;
    if (idx >= T_TOK * 32) return;
    int t = idx >> 5, i = idx & 31;
    int s = t & (SEQ - 1);
    float c  = g_cos[(s << 5) + i];
    float sn = g_sin[(s << 5) + i];
    const float* x = g_qkv_mixed + (size_t)t * NCAT1 + QLORA + KVLORA;
    float x1 = x[i], x2 = x[i + 32];
    size_t o = (size_t)t * CDIM + KVLORA;
    g_kfull[o + i]      = __float2half_rn(x1 * c  - x2 * sn);
    g_kfull[o + i + 32] = __float2half_rn(x1 * sn + x2 * c);
}

// q_rope: qcat fp16 cols [2048 + h*64 ...) -> qfull at [t, h*576+512 ...]
__global__ void rope_q_kernel()
{
    int idx = blockIdx.x * blockDim.x + threadIdx.x;
    if (idx >= T_TOK * NHEAD * 32) return;
    int t = idx >> 9;
    int rem = idx & 511;
    int h = rem >> 5, i = rem & 31;
    int s = t & (SEQ - 1);
    float c  = g_cos[(s << 5) + i];
    float sn = g_sin[(s << 5) + i];
    const __half* x = g_qcat + (size_t)t * NCAT2 + (NHEAD*DN) + h * DR;
    float x1 = __half2float(x[i]), x2 = __half2float(x[i + 32]);
    size_t o = (size_t)t * QF_LD + h * CDIM + KVLORA;
    g_qfull[o + i]      = __float2half_rn(x1 * c  - x2 * sn);
    g_qfull[o + i + 32] = __float2half_rn(x1 * sn + x2 * c);
}

__global__ void transpose_kup_kernel(const float* __restrict__ w_kvb)
{
    int idx = blockIdx.x * blockDim.x + threadIdx.x;
    if (idx >= NHEAD * KVLORA * DN) return;
    int h   = idx >> 16;
    int rem = idx & 65535;
    int r   = rem >> 7;
    int d   = rem & 127;
    g_kupT[idx] = __float2half_rn(w_kvb[(size_t)((h << 7) + d) * KVLORA + r]);
}

// kvlatT[b][r][k] = kfull[(b*SEQ+k)*576 + r]
__global__ void transpose_kv_kernel()
{
    int idx = blockIdx.x * blockDim.x + threadIdx.x;
    if (idx >= BATCH * KVLORA * SEQ) return;
    int b   = idx >> 20;
    int rem = idx & ((1 << 20) - 1);
    int r   = rem >> 11;
    int k   = rem & (SEQ - 1);
    g_kvlatT[idx] = g_kfull[(size_t)((b << 11) + k) * CDIM + r];
}

// ---------------- host ----------------
extern "C" void kernel_launch(void* const* d_in, const int* in_sizes, int n_in,
                              void* d_out, int out_size)
{
    (void)in_sizes; (void)n_in; (void)out_size;
    const float* hidden   = (const float*)d_in[0];
    const float* w_qa     = (const float*)d_in[1];
    const float* ln_qa_g  = (const float*)d_in[2];
    const float* ln_qa_b  = (const float*)d_in[3];
    const float* w_qb     = (const float*)d_in[4];
    const float* w_qrope  = (const float*)d_in[5];
    const float* w_kva    = (const float*)d_in[6];
    const float* ln_kva_g = (const float*)d_in[7];
    const float* ln_kva_b = (const float*)d_in[8];
    const float* w_kvb    = (const float*)d_in[9];
    const float* w_o      = (const float*)d_in[10];
    const int*   pos      = (const int*)d_in[11];
    float* out = (float*)d_out;

    cudaFuncSetAttribute(gemm_h, cudaFuncAttributeMaxDynamicSharedMemorySize, GSMEM_H);

    float *qkv_mixed, *rsum;
    __half *hid16,*wcat1,*wcat2,*wo16,*kupT16,*vup16;
    __half *qlat16,*qcat16,*qfull16,*kfull16,*kvlT16,*probs16,*attn16,*attnv16;
    cudaGetSymbolAddress((void**)&qkv_mixed, g_qkv_mixed);
    cudaGetSymbolAddress((void**)&rsum, g_rsum);
    cudaGetSymbolAddress((void**)&hid16, g_hidden);
    cudaGetSymbolAddress((void**)&wcat1, g_wcat1);
    cudaGetSymbolAddress((void**)&wcat2, g_wcat2);
    cudaGetSymbolAddress((void**)&wo16, g_wo);
    cudaGetSymbolAddress((void**)&kupT16, g_kupT);
    cudaGetSymbolAddress((void**)&vup16, g_vup);
    cudaGetSymbolAddress((void**)&qlat16, g_qlat);
    cudaGetSymbolAddress((void**)&qcat16, g_qcat);
    cudaGetSymbolAddress((void**)&qfull16, g_qfull);
    cudaGetSymbolAddress((void**)&kfull16, g_kfull);
    cudaGetSymbolAddress((void**)&kvlT16, g_kvlatT);
    cudaGetSymbolAddress((void**)&probs16, g_probs);
    cudaGetSymbolAddress((void**)&attn16, g_attn);
    cudaGetSymbolAddress((void**)&attnv16, g_attnv);

    auto cvt = [&](const float* x, __half* y, long long n) {
        long long n4 = n >> 2;
        cvt_half_kernel<<<(unsigned)((n4 + 255) / 256), 256>>>(
            (const float4*)x, (__half2*)y, n4);
    };
    auto gemmh = [&](const __half* Ap, const __half* Bp,
                     float* Cf, __half* Chf, const float* rsp, float escale,
                     int M, int N, int K, int lda, int ldb, int ldc,
                     int Z, int Hdim,
                     long long sAb, long long sAh, long long sBb, long long sBh,
                     long long sCb, long long sCh, int mode) {
        dim3 grid((N + 127) / 128, M / 128, Z);
        gemm_h<<<grid, 256, GSMEM_H>>>(Ap, Bp, Cf, Chf, rsp, escale,
                                       N, K, lda, ldb, ldc,
                                       sAb, sAh, sBb, sBh, sCb, sCh, Hdim, mode);
    };

    // ---- launches 1-3: conversions for the fused qa|kva GEMM ----
    cvt(hidden, hid16, (long long)T_TOK * DMODEL);                        // 1
    cvt(w_qa,   wcat1, (long long)QLORA * DMODEL);                        // 2
    cvt(w_kva,  wcat1 + (size_t)QLORA * DMODEL, (long long)CDIM * DMODEL);// 3

    // ---- launch 4: fused qa|kva projection (ncu target) ----
    gemmh(hid16, wcat1, qkv_mixed, nullptr, nullptr, 0.f,
          T_TOK, NCAT1, DMODEL, DMODEL, DMODEL, NCAT1, 1, 1, 0,0,0,0,0,0, 0);

    // ---- remaining conversions / setup ----
    cvt(w_qb,   wcat2, (long long)(NHEAD*DN) * QLORA);
    cvt(w_qrope,wcat2 + (size_t)(NHEAD*DN) * QLORA, (long long)(NHEAD*DR) * QLORA);
    cvt(w_o,    wo16,  (long long)DMODEL * (NHEAD*DV));
    cvt(w_kvb + (size_t)NHEAD * DN * KVLORA, vup16, (long long)NHEAD * DV * KVLORA);
    transpose_kup_kernel<<<(NHEAD * KVLORA * DN + 255) / 256, 256>>>(w_kvb);
    rope_tab_kernel<<<(SEQ * 32 + 255) / 256, 256>>>(pos);

    // LN q (cols 0..1535) -> qlat ; LN kv (cols 1536..2047) -> kfull[:, :512] ; rope_k
    ln_half_kernel<<<T_TOK, 256>>>(qkv_mixed, qlat16, ln_qa_g, ln_qa_b, QLORA, NCAT1, QLORA);
    ln_half_kernel<<<T_TOK, 256>>>(qkv_mixed + QLORA, kfull16, ln_kva_g, ln_kva_b, KVLORA, NCAT1, CDIM);
    rope_k_kernel<<<(T_TOK * 32 + 255) / 256, 256>>>();

    // fused qnope|qrope -> qcat fp16 ; rope_q reads cols 2048+
    gemmh(qlat16, wcat2, nullptr, qcat16, nullptr, 0.f,
          T_TOK, NCAT2, QLORA, QLORA, QLORA, NCAT2, 1, 1, 0,0,0,0,0,0, 1);
    rope_q_kernel<<<(T_TOK * NHEAD * 32 + 255) / 256, 256>>>();

    // absorb: qfull[:, h, :512] = qcat[:, h*128:(h+1)*128] @ kupT[h]^T
    gemmh(qcat16, kupT16, nullptr, qfull16, nullptr, 0.f,
          T_TOK, KVLORA, DN, NCAT2, DN, QF_LD, NHEAD, NHEAD,
          0, DN, 0, (long long)KVLORA * DN, 0, CDIM, 1);

    // kvlatT
    transpose_kv_kernel<<<(BATCH * KVLORA * SEQ + 255) / 256, 256>>>();

    // probs_unnorm = exp(scale * (qfull @ kfull^T))  (fp16 out, fused exp)
    float scale = (float)(1.0 / sqrt((double)(DN + DR)));
    gemmh(qfull16, kfull16, nullptr, probs16, nullptr, scale,
          SEQ, SEQ, CDIM, QF_LD, CDIM, SEQ, BATCH * NHEAD, NHEAD,
          (long long)SEQ * QF_LD, CDIM,
          (long long)SEQ * CDIM, 0,
          (long long)NHEAD * SEQ * SEQ, (long long)SEQ * SEQ, 2);

    // row sums of unnormalized probs
    rowsum_kernel<<<BATCH * NHEAD * SEQ / 8, 256>>>(probs16, rsum);

    // attn = (probs_unnorm @ kvlatT^T) / rsum  (fp16 out, fused normalize)
    gemmh(probs16, kvlT16, nullptr, attn16, rsum, 0.f,
          SEQ, KVLORA, SEQ, SEQ, SEQ, KVLORA, BATCH * NHEAD, NHEAD,
          (long long)NHEAD * SEQ * SEQ, (long long)SEQ * SEQ,
          (long long)KVLORA * SEQ, 0,
          (long long)NHEAD * SEQ * KVLORA, (long long)SEQ * KVLORA, 3);

    // attn_v = attn @ v_up^T  (fp16 out, strided into [b,s,h*DV])
    gemmh(attn16, vup16, nullptr, attnv16, nullptr, 0.f,
          SEQ, DV, KVLORA, KVLORA, KVLORA, NHEAD*DV, BATCH * NHEAD, NHEAD,
          (long long)NHEAD * SEQ * KVLORA, (long long)SEQ * KVLORA,
          0, (long long)DV * KVLORA,
          (long long)SEQ * (NHEAD*DV), DV, 1);

    // out = attn_v @ w_o^T  (f32 out)
    gemmh(attnv16, wo16, out, nullptr, nullptr, 0.f,
          T_TOK, DMODEL, NHEAD*DV, NHEAD*DV, NHEAD*DV, DMODEL, 1, 1,
          0,0,0,0,0,0, 0);
}